// round 14
// baseline (speedup 1.0000x reference)
#include <cuda_runtime.h>
#include <cuda_bf16.h>
#include <cstdint>
#include <math.h>

#define NN  50000
#define EE  800000
#define ET  850000
#define HD  128

// ---------------- weight-transpose offsets (elements) ----------------
#define OFF_WIN  0
#define OFF_PROJ 32768
#define OFF_WC   163840
#define OFF_F1   229376
#define OFF_F2   294912
#define OFF_PJ   327680
#define WTOT     393216

// ---------------- device scratch ----------------
__device__ float g_x4[NN*512];
__device__ float g_invn[4*NN];
__device__ float g_xaux[NN];
__device__ float g_bvec[256];
__device__ float g_bnstat[256];
__device__ float g_bnb[512];
__device__ float g_pjb[512];
__device__ int   g_deg_in[NN];
__device__ int   g_deg_out[NN];
__device__ int   g_off_in[NN+1];
__device__ int   g_off_out[NN+1];
__device__ int   g_cur_in[NN];
__device__ int   g_cur_out[NN];
__device__ int   g_col_in[ET];
__device__ int   g_col_out[ET];
__device__ __nv_bfloat16 g_xh [NN*256];
__device__ __nv_bfloat16 g_xlo[NN*256];
__device__ __nv_bfloat16 g_hh [NN*HD];
__device__ __nv_bfloat16 g_hl [NN*HD];
__device__ __nv_bfloat16 g_aggh[2*NN*HD];   // [dir0 | dir1]
__device__ __nv_bfloat16 g_aggl[2*NN*HD];
__device__ __nv_bfloat16 g_zh [NN*256];
__device__ __nv_bfloat16 g_zl [NN*256];
__device__ __nv_bfloat16 g_th [NN*HD];
__device__ __nv_bfloat16 g_tl [NN*HD];
__device__ __nv_bfloat16 g_wth[WTOT];
__device__ __nv_bfloat16 g_wtl[WTOT];

// ---------------- helpers ----------------
__device__ __forceinline__ uint32_t smem_u32(const void* p) {
    uint32_t a;
    asm("{ .reg .u64 t; cvta.to.shared.u64 t, %1; cvt.u32.u64 %0, t; }" : "=r"(a) : "l"(p));
    return a;
}
__device__ __forceinline__ void cp16(uint32_t s, const void* g, int sz) {
    asm volatile("cp.async.cg.shared.global [%0], [%1], 16, %2;"
                 :: "r"(s), "l"(g), "r"(sz));
}
#define LDSM4(R, addr) \
    asm volatile("ldmatrix.sync.aligned.m8n8.x4.shared.b16 {%0,%1,%2,%3}, [%4];" \
        : "=r"((R)[0]), "=r"((R)[1]), "=r"((R)[2]), "=r"((R)[3]) : "r"(addr))

__device__ __forceinline__ void mma16816(float* d, const uint32_t* a,
                                         uint32_t b0, uint32_t b1) {
    asm volatile("mma.sync.aligned.m16n8k16.row.col.f32.bf16.bf16.f32 "
        "{%0,%1,%2,%3}, {%4,%5,%6,%7}, {%8,%9}, {%0,%1,%2,%3};"
        : "+f"(d[0]), "+f"(d[1]), "+f"(d[2]), "+f"(d[3])
        : "r"(a[0]), "r"(a[1]), "r"(a[2]), "r"(a[3]), "r"(b0), "r"(b1));
}

__device__ __forceinline__ float gelu_f(float x) {
    return 0.5f * x * (1.0f + erff(x * 0.70710678118654752f));
}
__device__ __forceinline__ void split_bf16(float v, __nv_bfloat16& h, __nv_bfloat16& l) {
    h = __float2bfloat16(v);
    l = __float2bfloat16(v - __bfloat162float(h));
}

// ---------------- tiny utility kernels ----------------
__global__ void zero2_kernel(int* a, int* b, int n) {
    int i = blockIdx.x * blockDim.x + threadIdx.x;
    if (i < n) { a[i] = 0; b[i] = 0; }
}
__global__ void zero_float_kernel(float* p, int n) {
    int i = blockIdx.x * blockDim.x + threadIdx.x;
    if (i < n) p[i] = 0.0f;
}
__global__ void aux_kernel(const float* __restrict__ aux, const float* __restrict__ c,
                           const float* __restrict__ d, float* __restrict__ out) {
    int i = blockIdx.x * blockDim.x + threadIdx.x;
    if (i < NN) {
        float v = c[0] * aux[i] - d[0];
        out[i] = 1.0f / (1.0f + __expf(-v));
    }
}
__global__ void hist_kernel(const int* __restrict__ ei, int* __restrict__ din,
                            int* __restrict__ dout) {
    int e = blockIdx.x * blockDim.x + threadIdx.x;
    if (e >= EE) return;
    int s = ei[e];
    int d = ei[EE + e];
    atomicAdd(&dout[s], 1);
    atomicAdd(&din[d], 1);
}
__global__ void scan2_kernel(const int* __restrict__ degA, int* __restrict__ roffA,
                             int* __restrict__ curA, int* __restrict__ colA,
                             const int* __restrict__ degB, int* __restrict__ roffB,
                             int* __restrict__ curB, int* __restrict__ colB) {
    const int* deg  = blockIdx.x ? degB  : degA;
    int* roff       = blockIdx.x ? roffB : roffA;
    int* cursor     = blockIdx.x ? curB  : curA;
    int* colidx     = blockIdx.x ? colB  : colA;
    __shared__ int sh[1024];
    const int CH = (NN + 1023) / 1024;
    int t = threadIdx.x;
    int s0 = t * CH;
    int s1 = min(s0 + CH, NN);
    int sum = 0;
    for (int i = s0; i < s1; ++i) sum += deg[i] + 1;
    sh[t] = sum;
    __syncthreads();
    for (int off = 1; off < 1024; off <<= 1) {
        int v = (t >= off) ? sh[t - off] : 0;
        __syncthreads();
        sh[t] += v;
        __syncthreads();
    }
    int run = sh[t] - sum;
    if (t == 0) roff[0] = 0;
    for (int i = s0; i < s1; ++i) {
        int v = deg[i] + 1;
        colidx[run] = i;       // self loop first
        cursor[i] = run + 1;
        run += v;
        roff[i + 1] = run;
    }
}
__global__ void scatter_kernel(const int* __restrict__ ei, int* __restrict__ cin,
                               int* __restrict__ colin, int* __restrict__ cout,
                               int* __restrict__ colout) {
    int e = blockIdx.x * blockDim.x + threadIdx.x;
    if (e >= EE) return;
    int s = ei[e];
    int d = ei[EE + e];
    int p = atomicAdd(&cin[d], 1);  colin[p]  = s;
    int q = atomicAdd(&cout[s], 1); colout[q] = d;
}

// ---------------- BN fold into proj weights ----------------
__global__ void bnfold_w_kernel(const float* __restrict__ lin_l, const float* __restrict__ lin_r,
                                const float* __restrict__ stat, const float* __restrict__ gamma,
                                int layer,
                                __nv_bfloat16* __restrict__ wh, __nv_bfloat16* __restrict__ wl) {
    int e = blockIdx.y;
    int d = e >> 1;
    const float* src = ((e & 1) ? lin_r : lin_l) + (size_t)(layer * 2 + d) * 16384;
    int i = blockIdx.x * 256 + threadIdx.x;
    int k = i >> 7, n = i & 127;
    const float invN = 1.0f / (float)NN;
    float mu  = stat[k] * invN;
    float var = stat[128 + k] * invN - mu * mu;
    float s_k = gamma[k] * rsqrtf(var + 1e-5f);
    float w = src[(size_t)k * 128 + n] * s_k;
    __nv_bfloat16 h, l; split_bf16(w, h, l);
    size_t o = (size_t)OFF_PROJ + e * 16384 + (size_t)n * 128 + k;
    wh[o] = h; wl[o] = l;
}
__global__ void bnfold_b_kernel(const float* __restrict__ lin_l, const float* __restrict__ lin_r,
                                const float* __restrict__ stat, const float* __restrict__ gamma,
                                const float* __restrict__ beta, int layer,
                                float* __restrict__ bnb) {
    int n = threadIdx.x + blockIdx.x * blockDim.x;
    if (n >= 512) return;
    int e = n >> 7, nn = n & 127;
    int d = e >> 1;
    const float* src = ((e & 1) ? lin_r : lin_l) + (size_t)(layer * 2 + d) * 16384;
    const float invN = 1.0f / (float)NN;
    float acc = 0.f;
    for (int k = 0; k < 128; ++k) {
        float mu  = stat[k] * invN;
        float var = stat[128 + k] * invN - mu * mu;
        float s_k = gamma[k] * rsqrtf(var + 1e-5f);
        float t_k = beta[k] - mu * s_k;
        acc += t_k * src[(size_t)k * 128 + nn];
    }
    bnb[n] = acc;
}

// ---------------- ffn2(layer1) @ wproj fold ----------------
__global__ void pjfold_w_kernel(const float* __restrict__ ffw2, const float* __restrict__ wproj,
                                __nv_bfloat16* __restrict__ wh, __nv_bfloat16* __restrict__ wl) {
    int i = blockIdx.x * 256 + threadIdx.x;
    int n2 = i >> 7, k = i & 127;
    const float* w2row = ffw2 + (size_t)16384 + (size_t)k * 128;   // layer 1
    float acc = 0.f;
    for (int m = 0; m < 128; ++m) acc += w2row[m] * wproj[(size_t)m * 512 + n2];
    __nv_bfloat16 h, l; split_bf16(acc, h, l);
    size_t o = (size_t)OFF_PJ + (size_t)n2 * 128 + k;
    wh[o] = h; wl[o] = l;
}
__global__ void pjfold_b_kernel(const float* __restrict__ ffb2, const float* __restrict__ wproj,
                                const float* __restrict__ bproj, float* __restrict__ pjb) {
    int n2 = blockIdx.x * blockDim.x + threadIdx.x;
    if (n2 >= 512) return;
    const float* b2 = ffb2 + 128;   // layer 1
    float acc = bproj[n2];
    for (int m = 0; m < 128; ++m) acc += b2[m] * wproj[(size_t)m * 512 + n2];
    pjb[n2] = acc;
}

// ---------------- fused 4-section inverse-norm (+gate fold) ----------------
__global__ void invnorm4_kernel(const float* __restrict__ x4, const float* __restrict__ xaux,
                                float* __restrict__ invn) {
    int w = (blockIdx.x * blockDim.x + threadIdx.x) >> 5;
    int lane = threadIdx.x & 31;
    if (w >= NN) return;
    const float* row = x4 + (size_t)w * 512;
    float ss[4];
    #pragma unroll
    for (int s = 0; s < 4; ++s) {
        float4 v = *(const float4*)&row[s * 128 + lane * 4];
        ss[s] = v.x * v.x + v.y * v.y + v.z * v.z + v.w * v.w;
    }
    #pragma unroll
    for (int off = 16; off > 0; off >>= 1) {
        ss[0] += __shfl_xor_sync(0xffffffffu, ss[0], off);
        ss[1] += __shfl_xor_sync(0xffffffffu, ss[1], off);
        ss[2] += __shfl_xor_sync(0xffffffffu, ss[2], off);
        ss[3] += __shfl_xor_sync(0xffffffffu, ss[3], off);
    }
    if (lane == 0) {
        float gw = xaux[w] * 4.0f;
        invn[0 * NN + w] = gw / fmaxf(sqrtf(ss[0]), 1e-12f);
        invn[1 * NN + w] = 1.0f / fmaxf(sqrtf(ss[1]), 1e-12f);
        invn[2 * NN + w] = gw / fmaxf(sqrtf(ss[2]), 1e-12f);
        invn[3 * NN + w] = 1.0f / fmaxf(sqrtf(ss[3]), 1e-12f);
    }
}

// ---------------- bias @ wcat fold ----------------
__global__ void bvec_kernel(const float* __restrict__ bias, const float* __restrict__ wcat,
                            float* __restrict__ bvec) {
    int tid = threadIdx.x;
    int dir = tid >> 7, t = tid & 127;
    const float* b = bias + dir * 128;
    const float* w = wcat + dir * 128 * 128;
    float acc = 0.f;
    for (int k = 0; k < 128; ++k) acc += b[k] * w[k * 128 + t];
    bvec[tid] = acc;
}

// ---------------- GAT-COS aggregation (warp per node, unroll x4) -------------
__global__ void gat_kernel(const int* __restrict__ roff, const int* __restrict__ col,
                           const float* __restrict__ xl, const float* __restrict__ xr,
                           const float* __restrict__ gwl, const float* __restrict__ invr,
                           __nv_bfloat16* __restrict__ aggh, __nv_bfloat16* __restrict__ aggl) {
    const int LD = 512;
    int w = (blockIdx.x * blockDim.x + threadIdx.x) >> 5;
    int lane = threadIdx.x & 31;
    if (w >= NN) return;
    float inr = invr[w];
    float4 xri = *(const float4*)&xr[(size_t)w * LD + lane * 4];
    float4 nr = make_float4(xri.x * inr, xri.y * inr, xri.z * inr, xri.w * inr);
    float s = 0.f;
    float4 acc = make_float4(0.f, 0.f, 0.f, 0.f);
    int e = roff[w], e1 = roff[w + 1];
    for (; e + 4 <= e1; e += 4) {
        int j0 = col[e], j1 = col[e + 1], j2 = col[e + 2], j3 = col[e + 3];
        float4 x0 = *(const float4*)&xl[(size_t)j0 * LD + lane * 4];
        float4 x1 = *(const float4*)&xl[(size_t)j1 * LD + lane * 4];
        float4 x2 = *(const float4*)&xl[(size_t)j2 * LD + lane * 4];
        float4 x3 = *(const float4*)&xl[(size_t)j3 * LD + lane * 4];
        float g0 = gwl[j0], g1 = gwl[j1], g2 = gwl[j2], g3 = gwl[j3];
        float p0 = nr.x * x0.x + nr.y * x0.y + nr.z * x0.z + nr.w * x0.w;
        float p1 = nr.x * x1.x + nr.y * x1.y + nr.z * x1.z + nr.w * x1.w;
        float p2 = nr.x * x2.x + nr.y * x2.y + nr.z * x2.z + nr.w * x2.w;
        float p3 = nr.x * x3.x + nr.y * x3.y + nr.z * x3.z + nr.w * x3.w;
        #pragma unroll
        for (int off = 16; off > 0; off >>= 1) {
            p0 += __shfl_xor_sync(0xffffffffu, p0, off);
            p1 += __shfl_xor_sync(0xffffffffu, p1, off);
            p2 += __shfl_xor_sync(0xffffffffu, p2, off);
            p3 += __shfl_xor_sync(0xffffffffu, p3, off);
        }
        float q0 = __expf(g0 * fabsf(p0));
        float q1 = __expf(g1 * fabsf(p1));
        float q2 = __expf(g2 * fabsf(p2));
        float q3 = __expf(g3 * fabsf(p3));
        s += (q0 + q1) + (q2 + q3);
        acc.x += q0 * x0.x + q1 * x1.x + q2 * x2.x + q3 * x3.x;
        acc.y += q0 * x0.y + q1 * x1.y + q2 * x2.y + q3 * x3.y;
        acc.z += q0 * x0.z + q1 * x1.z + q2 * x2.z + q3 * x3.z;
        acc.w += q0 * x0.w + q1 * x1.w + q2 * x2.w + q3 * x3.w;
    }
    for (; e < e1; ++e) {
        int j0 = col[e];
        float4 x0 = *(const float4*)&xl[(size_t)j0 * LD + lane * 4];
        float g0 = gwl[j0];
        float p0 = nr.x * x0.x + nr.y * x0.y + nr.z * x0.z + nr.w * x0.w;
        #pragma unroll
        for (int off = 16; off > 0; off >>= 1)
            p0 += __shfl_xor_sync(0xffffffffu, p0, off);
        float q0 = __expf(g0 * fabsf(p0));
        s += q0;
        acc.x += q0 * x0.x; acc.y += q0 * x0.y;
        acc.z += q0 * x0.z; acc.w += q0 * x0.w;
    }
    float is = 1.0f / s;
    float o[4] = {acc.x * is, acc.y * is, acc.z * is, acc.w * is};
    size_t base = (size_t)w * HD + lane * 4;
    __nv_bfloat16 h0, l0, h1, l1, h2, l2, h3, l3;
    split_bf16(o[0], h0, l0); split_bf16(o[1], h1, l1);
    split_bf16(o[2], h2, l2); split_bf16(o[3], h3, l3);
    __nv_bfloat162 ha, hb, la, lb;
    ha.x = h0; ha.y = h1; hb.x = h2; hb.y = h3;
    la.x = l0; la.y = l1; lb.x = l2; lb.y = l3;
    *(__nv_bfloat162*)&aggh[base]     = ha;
    *(__nv_bfloat162*)&aggh[base + 2] = hb;
    *(__nv_bfloat162*)&aggl[base]     = la;
    *(__nv_bfloat162*)&aggl[base + 2] = lb;
}

// ---------------- input x -> bf16 hi/lo ----------------
__global__ void xconv_kernel(const float* __restrict__ x, __nv_bfloat16* __restrict__ xh,
                             __nv_bfloat16* __restrict__ xl, int n4) {
    int i = blockIdx.x * blockDim.x + threadIdx.x;
    if (i >= n4) return;
    float4 v = *(const float4*)&x[i * 4];
    __nv_bfloat16 h0, l0, h1, l1, h2, l2, h3, l3;
    split_bf16(v.x, h0, l0); split_bf16(v.y, h1, l1);
    split_bf16(v.z, h2, l2); split_bf16(v.w, h3, l3);
    __nv_bfloat162 ha, hb, la, lb;
    ha.x = h0; ha.y = h1; hb.x = h2; hb.y = h3;
    la.x = l0; la.y = l1; lb.x = l2; lb.y = l3;
    *(__nv_bfloat162*)&xh[i * 4]     = ha;
    *(__nv_bfloat162*)&xh[i * 4 + 2] = hb;
    *(__nv_bfloat162*)&xl[i * 4]     = la;
    *(__nv_bfloat162*)&xl[i * 4 + 2] = lb;
}

// ---------------- weight transpose + split ----------------
struct WTab {
    const float* src[8];
    int K[8];
    int N[8];
    int off[8];
};
__global__ void wconv_kernel(WTab tb, __nv_bfloat16* __restrict__ wh,
                             __nv_bfloat16* __restrict__ wl) {
    int e = blockIdx.y;
    int i = blockIdx.x * 256 + threadIdx.x;
    int K = tb.K[e], N = tb.N[e];
    if (i >= K * N) return;
    int k = i / N, n = i - k * N;
    float w = tb.src[e][(size_t)k * N + n];
    __nv_bfloat16 h, l; split_bf16(w, h, l);
    size_t o = (size_t)tb.off[e] + (size_t)n * K + k;
    wh[o] = h; wl[o] = l;
}

// ---------------- HMMA GEMM: single-chunk full-reuse, 2-stage pipeline --------
// Per K-32 slice: load Ah,Al,Bh,Bl once. MMA: Ah*Bh, Al*Bh (reuse B regs),
// Ah*Bl (reuse A regs).  STATS: accumulate column sum/sumsq into stat[256].
#define SM_STRIDE 80
#define TILE_B    10240
#define BUF_BYTES 40960
template<bool GELU, int OMODE, bool STATS>
__global__ void __launch_bounds__(256)
hmma_kernel(const __nv_bfloat16* __restrict__ Ah, const __nv_bfloat16* __restrict__ Al,
            const __nv_bfloat16* __restrict__ Bh, const __nv_bfloat16* __restrict__ Bl,
            float* __restrict__ C, __nv_bfloat16* __restrict__ Ch,
            __nv_bfloat16* __restrict__ Cl, const float* __restrict__ bias,
            float* __restrict__ stat,
            int M, int K, int ldc,
            int zsA, int zsB, int zsC, int zsBias)
{
    extern __shared__ char smem[];
    const uint32_t sbase = smem_u32(smem);
    const int tid = threadIdx.x, lane = tid & 31, wid = tid >> 5;
    const int warp_m = wid & 3, warp_n = wid >> 2;
    const int row0 = blockIdx.y * 128;
    const int col0 = blockIdx.x * 128;
    const int z = blockIdx.z;
    Ah += (size_t)z * zsA; Al += (size_t)z * zsA;
    Bh += (size_t)z * zsB; Bl += (size_t)z * zsB;
    if (C)  C  += (size_t)z * zsC;
    if (Ch) { Ch += (size_t)z * zsC; Cl += (size_t)z * zsC; }
    if (bias) bias += (size_t)z * zsBias;
    const int KB = K * 2;
    const int T = K >> 5;

    float acc[2][8][4];
    #pragma unroll
    for (int i = 0; i < 2; ++i)
        #pragma unroll
        for (int j = 0; j < 8; ++j)
            #pragma unroll
            for (int k = 0; k < 4; ++k) acc[i][j][k] = 0.f;

    auto load = [&](int c, int b) {
        const char* A0h = (const char*)Ah + (size_t)row0 * KB + c * 64;
        const char* A0l = (const char*)Al + (size_t)row0 * KB + c * 64;
        const char* B0h = (const char*)Bh + (size_t)col0 * KB + c * 64;
        const char* B0l = (const char*)Bl + (size_t)col0 * KB + c * 64;
        uint32_t s = sbase + b * BUF_BYTES;
        #pragma unroll
        for (int i = 0; i < 2; ++i) {
            int g = tid + i * 256;
            int r = g >> 2, ch = g & 3;
            uint32_t so = r * SM_STRIDE + ch * 16;
            size_t go = (size_t)r * KB + ch * 16;
            int sz = (row0 + r < M) ? 16 : 0;
            size_t goA = sz ? go : (size_t)(ch * 16);
            cp16(s + so,              A0h + goA, sz);
            cp16(s + TILE_B + so,     A0l + goA, sz);
            cp16(s + 2 * TILE_B + so, B0h + go, 16);
            cp16(s + 3 * TILE_B + so, B0l + go, 16);
        }
        asm volatile("cp.async.commit_group;" ::: "memory");
    };

    load(0, 0);

    for (int c = 0; c < T; ++c) {
        if (c + 1 < T) {
            load(c + 1, (c + 1) & 1);
            asm volatile("cp.async.wait_group 1;" ::: "memory");
        } else {
            asm volatile("cp.async.wait_group 0;" ::: "memory");
        }
        __syncthreads();

        uint32_t s = sbase + (c & 1) * BUF_BYTES;
        #pragma unroll
        for (int ks = 0; ks < 2; ++ks) {
            uint32_t bb[4][4];
            #pragma unroll
            for (int fb = 0; fb < 4; ++fb) {
                int rn = warp_n * 64 + fb * 16 + (lane & 7) + ((lane >> 4) << 3);
                uint32_t bd = s + 2 * TILE_B + rn * SM_STRIDE + ks * 32 + (((lane >> 3) & 1) << 4);
                LDSM4(bb[fb], bd);
            }
            uint32_t ah[2][4];
            #pragma unroll
            for (int fm = 0; fm < 2; ++fm) {
                int rr = warp_m * 32 + fm * 16 + (lane & 15);
                uint32_t ad = s + rr * SM_STRIDE + ks * 32 + ((lane >> 4) << 4);
                LDSM4(ah[fm], ad);
            }
            #pragma unroll
            for (int fm = 0; fm < 2; ++fm)
                #pragma unroll
                for (int fb = 0; fb < 4; ++fb) {
                    mma16816(acc[fm][fb * 2],     ah[fm], bb[fb][0], bb[fb][1]);
                    mma16816(acc[fm][fb * 2 + 1], ah[fm], bb[fb][2], bb[fb][3]);
                }
            // Al section (reuse bb)
            uint32_t al[2][4];
            #pragma unroll
            for (int fm = 0; fm < 2; ++fm) {
                int rr = warp_m * 32 + fm * 16 + (lane & 15);
                uint32_t ad = s + TILE_B + rr * SM_STRIDE + ks * 32 + ((lane >> 4) << 4);
                LDSM4(al[fm], ad);
            }
            #pragma unroll
            for (int fm = 0; fm < 2; ++fm)
                #pragma unroll
                for (int fb = 0; fb < 4; ++fb) {
                    mma16816(acc[fm][fb * 2],     al[fm], bb[fb][0], bb[fb][1]);
                    mma16816(acc[fm][fb * 2 + 1], al[fm], bb[fb][2], bb[fb][3]);
                }
            // Bl section (reuse ah)
            #pragma unroll
            for (int fb = 0; fb < 4; ++fb) {
                int rn = warp_n * 64 + fb * 16 + (lane & 7) + ((lane >> 4) << 3);
                uint32_t bd = s + 3 * TILE_B + rn * SM_STRIDE + ks * 32 + (((lane >> 3) & 1) << 4);
                LDSM4(bb[fb], bd);
            }
            #pragma unroll
            for (int fm = 0; fm < 2; ++fm)
                #pragma unroll
                for (int fb = 0; fb < 4; ++fb) {
                    mma16816(acc[fm][fb * 2],     ah[fm], bb[fb][0], bb[fb][1]);
                    mma16816(acc[fm][fb * 2 + 1], ah[fm], bb[fb][2], bb[fb][3]);
                }
        }
        __syncthreads();
    }

    // stats buffer in smem (tiles no longer needed)
    float* cs = (float*)smem;
    if (STATS) {
        if (tid < 256) cs[tid] = 0.f;
        __syncthreads();
    }

    // epilogue
    #pragma unroll
    for (int fm = 0; fm < 2; ++fm) {
        int rbase = row0 + warp_m * 32 + fm * 16 + (lane >> 2);
        #pragma unroll
        for (int half = 0; half < 2; ++half) {
            int r = rbase + half * 8;
            if (r >= M) continue;
            #pragma unroll
            for (int fn = 0; fn < 8; ++fn) {
                int cc = col0 + warp_n * 64 + fn * 8 + (lane & 3) * 2;
                float v0 = acc[fm][fn][half * 2];
                float v1 = acc[fm][fn][half * 2 + 1];
                if (bias) { v0 += bias[cc]; v1 += bias[cc + 1]; }
                if (GELU) { v0 = gelu_f(v0); v1 = gelu_f(v1); }
                if (STATS) {
                    atomicAdd(&cs[cc], v0);
                    atomicAdd(&cs[128 + cc], v0 * v0);
                    atomicAdd(&cs[cc + 1], v1);
                    atomicAdd(&cs[128 + cc + 1], v1 * v1);
                }
                size_t o = (size_t)r * ldc + cc;
                if (OMODE == 0 || OMODE == 2) {
                    float2 f2 = make_float2(v0, v1);
                    *(float2*)&C[o] = f2;
                }
                if (OMODE == 1 || OMODE == 2) {
                    __nv_bfloat16 h0, l0, h1, l1;
                    split_bf16(v0, h0, l0); split_bf16(v1, h1, l1);
                    __nv_bfloat162 hp, lp;
                    hp.x = h0; hp.y = h1; lp.x = l0; lp.y = l1;
                    *(__nv_bfloat162*)&Ch[o] = hp;
                    *(__nv_bfloat162*)&Cl[o] = lp;
                }
            }
        }
    }
    if (STATS) {
        __syncthreads();
        if (tid < 256) atomicAdd(&stat[tid], cs[tid]);
    }
}

// ---------------- host ----------------
static void* sym(const void* s) {
    void* p = nullptr;
    cudaGetSymbolAddress(&p, s);
    return p;
}

#define SMEM_HM (2 * BUF_BYTES)

extern "C" void kernel_launch(void* const* d_in, const int* in_sizes, int n_in,
                              void* d_out, int out_size) {
    const float* x      = (const float*)d_in[0];
    const int*   ei     = (const int*)  d_in[1];
    const float* nsa    = (const float*)d_in[2];
    const float* c_p    = (const float*)d_in[3];
    const float* d_p    = (const float*)d_in[4];
    const float* w_in   = (const float*)d_in[5];
    const float* b_in   = (const float*)d_in[6];
    const float* bn_g   = (const float*)d_in[7];
    const float* bn_b   = (const float*)d_in[8];
    const float* lin_l  = (const float*)d_in[9];
    const float* lin_r  = (const float*)d_in[10];
    const float* attb   = (const float*)d_in[11];
    const float* wcat   = (const float*)d_in[12];
    const float* ffw1   = (const float*)d_in[13];
    const float* ffb1   = (const float*)d_in[14];
    const float* ffw2   = (const float*)d_in[15];
    const float* ffb2   = (const float*)d_in[16];
    const float* wproj  = (const float*)d_in[17];
    const float* bproj  = (const float*)d_in[18];
    float* out = (float*)d_out;

    float* p_x4   = (float*)sym(g_x4);
    float* p_invn = (float*)sym(g_invn);
    float* p_xaux = (float*)sym(g_xaux);
    float* p_bvec = (float*)sym(g_bvec);
    float* p_bn   = (float*)sym(g_bnstat);
    float* p_bnb  = (float*)sym(g_bnb);
    float* p_pjb  = (float*)sym(g_pjb);
    int* p_din  = (int*)sym(g_deg_in);
    int* p_dout = (int*)sym(g_deg_out);
    int* p_oin  = (int*)sym(g_off_in);
    int* p_oout = (int*)sym(g_off_out);
    int* p_cin  = (int*)sym(g_cur_in);
    int* p_cout = (int*)sym(g_cur_out);
    int* p_colin  = (int*)sym(g_col_in);
    int* p_colout = (int*)sym(g_col_out);
    __nv_bfloat16* p_xh   = (__nv_bfloat16*)sym(g_xh);
    __nv_bfloat16* p_xlo  = (__nv_bfloat16*)sym(g_xlo);
    __nv_bfloat16* p_hh   = (__nv_bfloat16*)sym(g_hh);
    __nv_bfloat16* p_hl   = (__nv_bfloat16*)sym(g_hl);
    __nv_bfloat16* p_aggh = (__nv_bfloat16*)sym(g_aggh);
    __nv_bfloat16* p_aggl = (__nv_bfloat16*)sym(g_aggl);
    __nv_bfloat16* p_zh   = (__nv_bfloat16*)sym(g_zh);
    __nv_bfloat16* p_zl   = (__nv_bfloat16*)sym(g_zl);
    __nv_bfloat16* p_th   = (__nv_bfloat16*)sym(g_th);
    __nv_bfloat16* p_tl   = (__nv_bfloat16*)sym(g_tl);
    __nv_bfloat16* p_wth  = (__nv_bfloat16*)sym(g_wth);
    __nv_bfloat16* p_wtl  = (__nv_bfloat16*)sym(g_wtl);

    cudaFuncSetAttribute(hmma_kernel<false, 0, false>, cudaFuncAttributeMaxDynamicSharedMemorySize, SMEM_HM);
    cudaFuncSetAttribute(hmma_kernel<true,  1, false>, cudaFuncAttributeMaxDynamicSharedMemorySize, SMEM_HM);
    cudaFuncSetAttribute(hmma_kernel<false, 1, true>,  cudaFuncAttributeMaxDynamicSharedMemorySize, SMEM_HM);

    const int MB = (NN + 127) / 128;   // 391
    dim3 g1(1, MB), g4(4, MB), gz(1, MB, 2);
    const int gatBlocks = (NN * 32 + 255) / 256;
    const int NNHD = NN * HD;

    // ---- operand conversions ----
    xconv_kernel<<<(NN * 256 / 4 + 255) / 256, 256>>>(x, p_xh, p_xlo, NN * 256 / 4);
    WTab tb;
    int e = 0;
    tb.src[e] = w_in; tb.K[e] = 256; tb.N[e] = 128; tb.off[e] = OFF_WIN; ++e;
    for (int i = 0; i < 4; ++i) { tb.src[e] = wcat + (size_t)i * 16384; tb.K[e] = 128; tb.N[e] = 128; tb.off[e] = OFF_WC + i * 16384; ++e; }
    for (int i = 0; i < 2; ++i) { tb.src[e] = ffw1 + (size_t)i * 32768; tb.K[e] = 256; tb.N[e] = 128; tb.off[e] = OFF_F1 + i * 32768; ++e; }
    tb.src[e] = ffw2; tb.K[e] = 128; tb.N[e] = 128; tb.off[e] = OFF_F2; ++e;   // layer 0 only
    wconv_kernel<<<dim3(256, 8), 256>>>(tb, p_wth, p_wtl);
    aux_kernel<<<(NN + 255) / 256, 256>>>(nsa, c_p, d_p, p_xaux);
    zero_float_kernel<<<1, 256>>>(p_bn, 256);

    // ---- (launch #5) input projection with fused BN stats ----
    hmma_kernel<false, 1, true><<<g1, 256, SMEM_HM>>>(p_xh, p_xlo, p_wth + OFF_WIN, p_wtl + OFF_WIN,
        nullptr, p_hh, p_hl, b_in, p_bn, NN, 256, HD, 0, 0, 0, 0);

    // ---- folded final weights (independent) ----
    pjfold_w_kernel<<<256, 256>>>(ffw2, wproj, p_wth, p_wtl);
    pjfold_b_kernel<<<2, 256>>>(ffb2, wproj, bproj, p_pjb);

    // ---- CSR build ----
    zero2_kernel<<<(NN + 255) / 256, 256>>>(p_din, p_dout, NN);
    hist_kernel<<<(EE + 255) / 256, 256>>>(ei, p_din, p_dout);
    scan2_kernel<<<2, 1024>>>(p_din, p_oin, p_cin, p_colin,
                              p_dout, p_oout, p_cout, p_colout);
    scatter_kernel<<<(EE + 255) / 256, 256>>>(ei, p_cin, p_colin, p_cout, p_colout);

    for (int l = 0; l < 2; ++l) {
        bnfold_w_kernel<<<dim3(64, 4), 256>>>(lin_l, lin_r, p_bn, bn_g + l * HD, l, p_wth, p_wtl);
        bnfold_b_kernel<<<2, 256>>>(lin_l, lin_r, p_bn, bn_g + l * HD, bn_b + l * HD, l, p_bnb);

        // fused projection: x4 = h @ W' + bnb  (N=512)
        hmma_kernel<false, 0, false><<<g4, 256, SMEM_HM>>>(p_hh, p_hl,
            p_wth + OFF_PROJ, p_wtl + OFF_PROJ,
            p_x4, nullptr, nullptr, p_bnb, nullptr, NN, 128, 512, 0, 0, 0, 0);

        invnorm4_kernel<<<gatBlocks, 256>>>(p_x4, p_xaux, p_invn);
        bvec_kernel<<<1, 256>>>(attb + (size_t)l * 256, wcat + (size_t)l * 2 * HD * HD, p_bvec);

        gat_kernel<<<gatBlocks, 256>>>(p_oin, p_colin, p_x4, p_x4 + 128,
                                       p_invn + 0 * NN, p_invn + 1 * NN, p_aggh, p_aggl);
        gat_kernel<<<gatBlocks, 256>>>(p_oout, p_colout, p_x4 + 256, p_x4 + 384,
                                       p_invn + 2 * NN, p_invn + 3 * NN,
                                       p_aggh + NNHD, p_aggl + NNHD);

        int i0 = l * 2;
        // merged wcat pair
        hmma_kernel<true, 1, false><<<gz, 256, SMEM_HM>>>(p_aggh, p_aggl,
            p_wth + OFF_WC + i0 * 16384, p_wtl + OFF_WC + i0 * 16384,
            nullptr, p_zh, p_zl, p_bvec, nullptr, NN, 128, 256,
            NNHD, 16384, 128, 128);

        hmma_kernel<true, 1, false><<<g1, 256, SMEM_HM>>>(p_zh, p_zl, p_wth + OFF_F1 + l * 32768,
            p_wtl + OFF_F1 + l * 32768, nullptr, p_th, p_tl, ffb1 + l * HD, nullptr,
            NN, 256, HD, 0, 0, 0, 0);

        if (l == 0) {
            zero_float_kernel<<<1, 256>>>(p_bn, 256);
            hmma_kernel<false, 1, true><<<g1, 256, SMEM_HM>>>(p_th, p_tl, p_wth + OFF_F2,
                p_wtl + OFF_F2, nullptr, p_hh, p_hl, ffb2, p_bn, NN, 128, HD, 0, 0, 0, 0);
        } else {
            // folded ffn2(l1) + final projection -> d_out [NN, 512]
            hmma_kernel<false, 0, false><<<g4, 256, SMEM_HM>>>(p_th, p_tl, p_wth + OFF_PJ,
                p_wtl + OFF_PJ, out, nullptr, nullptr, p_pjb, nullptr, NN, 128, 512, 0, 0, 0, 0);
        }
    }
}

// round 15
// speedup vs baseline: 1.2398x; 1.2398x over previous
#include <cuda_runtime.h>
#include <cuda_bf16.h>
#include <cstdint>
#include <math.h>

#define NN  50000
#define EE  800000
#define ET  850000
#define HD  128

// ---------------- weight-transpose offsets (elements) ----------------
#define OFF_WIN  0
#define OFF_PROJ 32768
#define OFF_WC   163840
#define OFF_F1   229376
#define OFF_F2   294912
#define OFF_PJ   327680
#define WTOT     393216

// ---------------- device scratch ----------------
__device__ float g_x4[NN*512];
__device__ float g_invn[4*NN];
__device__ float g_xaux[NN];
__device__ float g_bvec[256];
__device__ float g_bnstat[256];
__device__ float g_bnb[512];
__device__ float g_pjb[512];
__device__ int   g_deg_in[NN];
__device__ int   g_deg_out[NN];
__device__ int   g_off_in[NN+1];
__device__ int   g_off_out[NN+1];
__device__ int   g_cur_in[NN];
__device__ int   g_cur_out[NN];
__device__ int   g_col_in[ET];
__device__ int   g_col_out[ET];
__device__ __nv_bfloat16 g_xh [NN*256];
__device__ __nv_bfloat16 g_xlo[NN*256];
__device__ __nv_bfloat16 g_hh [NN*HD];
__device__ __nv_bfloat16 g_hl [NN*HD];
__device__ __nv_bfloat16 g_aggh[2*NN*HD];
__device__ __nv_bfloat16 g_aggl[2*NN*HD];
__device__ __nv_bfloat16 g_zh [NN*256];
__device__ __nv_bfloat16 g_zl [NN*256];
__device__ __nv_bfloat16 g_th [NN*HD];
__device__ __nv_bfloat16 g_tl [NN*HD];
__device__ __nv_bfloat16 g_wth[WTOT];
__device__ __nv_bfloat16 g_wtl[WTOT];

// ---------------- helpers ----------------
__device__ __forceinline__ uint32_t smem_u32(const void* p) {
    uint32_t a;
    asm("{ .reg .u64 t; cvta.to.shared.u64 t, %1; cvt.u32.u64 %0, t; }" : "=r"(a) : "l"(p));
    return a;
}
__device__ __forceinline__ void cp16(uint32_t s, const void* g, int sz) {
    asm volatile("cp.async.cg.shared.global [%0], [%1], 16, %2;"
                 :: "r"(s), "l"(g), "r"(sz));
}
#define LDSM4(R, addr) \
    asm volatile("ldmatrix.sync.aligned.m8n8.x4.shared.b16 {%0,%1,%2,%3}, [%4];" \
        : "=r"((R)[0]), "=r"((R)[1]), "=r"((R)[2]), "=r"((R)[3]) : "r"(addr))

__device__ __forceinline__ void mma16816(float* d, const uint32_t* a,
                                         uint32_t b0, uint32_t b1) {
    asm volatile("mma.sync.aligned.m16n8k16.row.col.f32.bf16.bf16.f32 "
        "{%0,%1,%2,%3}, {%4,%5,%6,%7}, {%8,%9}, {%0,%1,%2,%3};"
        : "+f"(d[0]), "+f"(d[1]), "+f"(d[2]), "+f"(d[3])
        : "r"(a[0]), "r"(a[1]), "r"(a[2]), "r"(a[3]), "r"(b0), "r"(b1));
}

__device__ __forceinline__ float gelu_f(float x) {
    return 0.5f * x * (1.0f + erff(x * 0.70710678118654752f));
}
__device__ __forceinline__ void split_bf16(float v, __nv_bfloat16& h, __nv_bfloat16& l) {
    h = __float2bfloat16(v);
    l = __float2bfloat16(v - __bfloat162float(h));
}

// ---------------- tiny utility kernels ----------------
__global__ void zero2_kernel(int* a, int* b, int n) {
    int i = blockIdx.x * blockDim.x + threadIdx.x;
    if (i < n) { a[i] = 0; b[i] = 0; }
}
__global__ void zero_float_kernel(float* p, int n) {
    int i = blockIdx.x * blockDim.x + threadIdx.x;
    if (i < n) p[i] = 0.0f;
}
__global__ void hist_kernel(const int* __restrict__ ei, int* __restrict__ din,
                            int* __restrict__ dout) {
    int e = blockIdx.x * blockDim.x + threadIdx.x;
    if (e >= EE) return;
    int s = ei[e];
    int d = ei[EE + e];
    atomicAdd(&dout[s], 1);
    atomicAdd(&din[d], 1);
}
__global__ void scan2_kernel(const int* __restrict__ degA, int* __restrict__ roffA,
                             int* __restrict__ curA, int* __restrict__ colA,
                             const int* __restrict__ degB, int* __restrict__ roffB,
                             int* __restrict__ curB, int* __restrict__ colB) {
    const int* deg  = blockIdx.x ? degB  : degA;
    int* roff       = blockIdx.x ? roffB : roffA;
    int* cursor     = blockIdx.x ? curB  : curA;
    int* colidx     = blockIdx.x ? colB  : colA;
    __shared__ int sh[1024];
    const int CH = (NN + 1023) / 1024;
    int t = threadIdx.x;
    int s0 = t * CH;
    int s1 = min(s0 + CH, NN);
    int sum = 0;
    for (int i = s0; i < s1; ++i) sum += deg[i] + 1;
    sh[t] = sum;
    __syncthreads();
    for (int off = 1; off < 1024; off <<= 1) {
        int v = (t >= off) ? sh[t - off] : 0;
        __syncthreads();
        sh[t] += v;
        __syncthreads();
    }
    int run = sh[t] - sum;
    if (t == 0) roff[0] = 0;
    for (int i = s0; i < s1; ++i) {
        int v = deg[i] + 1;
        colidx[run] = i;       // self loop first
        cursor[i] = run + 1;
        run += v;
        roff[i + 1] = run;
    }
}
__global__ void scatter_kernel(const int* __restrict__ ei, int* __restrict__ cin,
                               int* __restrict__ colin, int* __restrict__ cout,
                               int* __restrict__ colout) {
    int e = blockIdx.x * blockDim.x + threadIdx.x;
    if (e >= EE) return;
    int s = ei[e];
    int d = ei[EE + e];
    int p = atomicAdd(&cin[d], 1);  colin[p]  = s;
    int q = atomicAdd(&cout[s], 1); colout[q] = d;
}

// ---------------- batchnorm stats from bf16 hi/lo ----------------
__global__ void bn_reduce_kernel(const __nv_bfloat16* __restrict__ hh,
                                 const __nv_bfloat16* __restrict__ hl,
                                 float* __restrict__ stat) {
    int col = threadIdx.x;
    float s = 0.f, ss = 0.f;
    for (int r = blockIdx.x; r < NN; r += gridDim.x) {
        size_t o = (size_t)r * HD + col;
        float v = __bfloat162float(hh[o]) + __bfloat162float(hl[o]);
        s += v; ss += v * v;
    }
    atomicAdd(&stat[col], s);
    atomicAdd(&stat[128 + col], ss);
}

// ---------------- merged BN fold (weights + bias + bvec) ----------------
// blockIdx.y 0..3: weight matrices; y==4 (x<2): BN bias; y==5 (x==0): bvec.
__global__ void bnfold_kernel(const float* __restrict__ lin_l, const float* __restrict__ lin_r,
                              const float* __restrict__ stat, const float* __restrict__ gamma,
                              const float* __restrict__ beta, int layer,
                              const float* __restrict__ attb, const float* __restrict__ wcat,
                              __nv_bfloat16* __restrict__ wh, __nv_bfloat16* __restrict__ wl,
                              float* __restrict__ bnb, float* __restrict__ bvec) {
    int y = blockIdx.y;
    const float invN = 1.0f / (float)NN;
    if (y < 4) {
        int e = y, d = e >> 1;
        const float* src = ((e & 1) ? lin_r : lin_l) + (size_t)(layer * 2 + d) * 16384;
        int i = blockIdx.x * 256 + threadIdx.x;
        int k = i >> 7, n = i & 127;
        float mu  = stat[k] * invN;
        float var = stat[128 + k] * invN - mu * mu;
        float s_k = gamma[k] * rsqrtf(var + 1e-5f);
        float w = src[(size_t)k * 128 + n] * s_k;
        __nv_bfloat16 h, l; split_bf16(w, h, l);
        size_t o = (size_t)OFF_PROJ + e * 16384 + (size_t)n * 128 + k;
        wh[o] = h; wl[o] = l;
    } else if (y == 4) {
        int n = blockIdx.x * 256 + threadIdx.x;
        if (n >= 512) return;
        int e = n >> 7, nn = n & 127;
        int d = e >> 1;
        const float* src = ((e & 1) ? lin_r : lin_l) + (size_t)(layer * 2 + d) * 16384;
        float acc = 0.f;
        for (int k = 0; k < 128; ++k) {
            float mu  = stat[k] * invN;
            float var = stat[128 + k] * invN - mu * mu;
            float s_k = gamma[k] * rsqrtf(var + 1e-5f);
            float t_k = beta[k] - mu * s_k;
            acc += t_k * src[(size_t)k * 128 + nn];
        }
        bnb[n] = acc;
    } else {
        if (blockIdx.x != 0) return;
        int tid = threadIdx.x;
        int dir = tid >> 7, t = tid & 127;
        const float* b = attb + (size_t)layer * 256 + dir * 128;
        const float* w = wcat + (size_t)layer * 2 * HD * HD + (size_t)dir * 128 * 128;
        float acc = 0.f;
        for (int k = 0; k < 128; ++k) acc += b[k] * w[k * 128 + t];
        bvec[tid] = acc;
    }
}

// ---------------- merged ffn2(l1)@wproj fold (weights + bias) ----------------
__global__ void pjfold_kernel(const float* __restrict__ ffw2, const float* __restrict__ wproj,
                              const float* __restrict__ ffb2, const float* __restrict__ bproj,
                              __nv_bfloat16* __restrict__ wh, __nv_bfloat16* __restrict__ wl,
                              float* __restrict__ pjb) {
    if (blockIdx.x < 256) {
        int i = blockIdx.x * 256 + threadIdx.x;
        int n2 = i >> 7, k = i & 127;
        const float* w2row = ffw2 + (size_t)16384 + (size_t)k * 128;   // layer 1
        float acc = 0.f;
        for (int m = 0; m < 128; ++m) acc += w2row[m] * wproj[(size_t)m * 512 + n2];
        __nv_bfloat16 h, l; split_bf16(acc, h, l);
        size_t o = (size_t)OFF_PJ + (size_t)n2 * 128 + k;
        wh[o] = h; wl[o] = l;
    } else {
        int n2 = (blockIdx.x - 256) * 256 + threadIdx.x;
        if (n2 >= 512) return;
        const float* b2 = ffb2 + 128;   // layer 1
        float acc = bproj[n2];
        for (int m = 0; m < 128; ++m) acc += b2[m] * wproj[(size_t)m * 512 + n2];
        pjb[n2] = acc;
    }
}

// ---------------- fused 4-section inverse-norm (+gate fold) ----------------
__global__ void invnorm4_kernel(const float* __restrict__ x4, const float* __restrict__ xaux,
                                float* __restrict__ invn) {
    int w = (blockIdx.x * blockDim.x + threadIdx.x) >> 5;
    int lane = threadIdx.x & 31;
    if (w >= NN) return;
    const float* row = x4 + (size_t)w * 512;
    float ss[4];
    #pragma unroll
    for (int s = 0; s < 4; ++s) {
        float4 v = *(const float4*)&row[s * 128 + lane * 4];
        ss[s] = v.x * v.x + v.y * v.y + v.z * v.z + v.w * v.w;
    }
    #pragma unroll
    for (int off = 16; off > 0; off >>= 1) {
        ss[0] += __shfl_xor_sync(0xffffffffu, ss[0], off);
        ss[1] += __shfl_xor_sync(0xffffffffu, ss[1], off);
        ss[2] += __shfl_xor_sync(0xffffffffu, ss[2], off);
        ss[3] += __shfl_xor_sync(0xffffffffu, ss[3], off);
    }
    if (lane == 0) {
        float gw = xaux[w] * 4.0f;
        invn[0 * NN + w] = gw / fmaxf(sqrtf(ss[0]), 1e-12f);
        invn[1 * NN + w] = 1.0f / fmaxf(sqrtf(ss[1]), 1e-12f);
        invn[2 * NN + w] = gw / fmaxf(sqrtf(ss[2]), 1e-12f);
        invn[3 * NN + w] = 1.0f / fmaxf(sqrtf(ss[3]), 1e-12f);
    }
}

// ---------------- GAT-COS aggregation (warp per node, unroll x4) -------------
__global__ void gat_kernel(const int* __restrict__ roff, const int* __restrict__ col,
                           const float* __restrict__ xl, const float* __restrict__ xr,
                           const float* __restrict__ gwl, const float* __restrict__ invr,
                           __nv_bfloat16* __restrict__ aggh, __nv_bfloat16* __restrict__ aggl) {
    const int LD = 512;
    int w = (blockIdx.x * blockDim.x + threadIdx.x) >> 5;
    int lane = threadIdx.x & 31;
    if (w >= NN) return;
    float inr = invr[w];
    float4 xri = *(const float4*)&xr[(size_t)w * LD + lane * 4];
    float4 nr = make_float4(xri.x * inr, xri.y * inr, xri.z * inr, xri.w * inr);
    float s = 0.f;
    float4 acc = make_float4(0.f, 0.f, 0.f, 0.f);
    int e = roff[w], e1 = roff[w + 1];
    for (; e + 4 <= e1; e += 4) {
        int j0 = col[e], j1 = col[e + 1], j2 = col[e + 2], j3 = col[e + 3];
        float4 x0 = *(const float4*)&xl[(size_t)j0 * LD + lane * 4];
        float4 x1 = *(const float4*)&xl[(size_t)j1 * LD + lane * 4];
        float4 x2 = *(const float4*)&xl[(size_t)j2 * LD + lane * 4];
        float4 x3 = *(const float4*)&xl[(size_t)j3 * LD + lane * 4];
        float g0 = gwl[j0], g1 = gwl[j1], g2 = gwl[j2], g3 = gwl[j3];
        float p0 = nr.x * x0.x + nr.y * x0.y + nr.z * x0.z + nr.w * x0.w;
        float p1 = nr.x * x1.x + nr.y * x1.y + nr.z * x1.z + nr.w * x1.w;
        float p2 = nr.x * x2.x + nr.y * x2.y + nr.z * x2.z + nr.w * x2.w;
        float p3 = nr.x * x3.x + nr.y * x3.y + nr.z * x3.z + nr.w * x3.w;
        #pragma unroll
        for (int off = 16; off > 0; off >>= 1) {
            p0 += __shfl_xor_sync(0xffffffffu, p0, off);
            p1 += __shfl_xor_sync(0xffffffffu, p1, off);
            p2 += __shfl_xor_sync(0xffffffffu, p2, off);
            p3 += __shfl_xor_sync(0xffffffffu, p3, off);
        }
        float q0 = __expf(g0 * fabsf(p0));
        float q1 = __expf(g1 * fabsf(p1));
        float q2 = __expf(g2 * fabsf(p2));
        float q3 = __expf(g3 * fabsf(p3));
        s += (q0 + q1) + (q2 + q3);
        acc.x += q0 * x0.x + q1 * x1.x + q2 * x2.x + q3 * x3.x;
        acc.y += q0 * x0.y + q1 * x1.y + q2 * x2.y + q3 * x3.y;
        acc.z += q0 * x0.z + q1 * x1.z + q2 * x2.z + q3 * x3.z;
        acc.w += q0 * x0.w + q1 * x1.w + q2 * x2.w + q3 * x3.w;
    }
    for (; e < e1; ++e) {
        int j0 = col[e];
        float4 x0 = *(const float4*)&xl[(size_t)j0 * LD + lane * 4];
        float g0 = gwl[j0];
        float p0 = nr.x * x0.x + nr.y * x0.y + nr.z * x0.z + nr.w * x0.w;
        #pragma unroll
        for (int off = 16; off > 0; off >>= 1)
            p0 += __shfl_xor_sync(0xffffffffu, p0, off);
        float q0 = __expf(g0 * fabsf(p0));
        s += q0;
        acc.x += q0 * x0.x; acc.y += q0 * x0.y;
        acc.z += q0 * x0.z; acc.w += q0 * x0.w;
    }
    float is = 1.0f / s;
    float o[4] = {acc.x * is, acc.y * is, acc.z * is, acc.w * is};
    size_t base = (size_t)w * HD + lane * 4;
    __nv_bfloat16 h0, l0, h1, l1, h2, l2, h3, l3;
    split_bf16(o[0], h0, l0); split_bf16(o[1], h1, l1);
    split_bf16(o[2], h2, l2); split_bf16(o[3], h3, l3);
    __nv_bfloat162 ha, hb, la, lb;
    ha.x = h0; ha.y = h1; hb.x = h2; hb.y = h3;
    la.x = l0; la.y = l1; lb.x = l2; lb.y = l3;
    *(__nv_bfloat162*)&aggh[base]     = ha;
    *(__nv_bfloat162*)&aggh[base + 2] = hb;
    *(__nv_bfloat162*)&aggl[base]     = la;
    *(__nv_bfloat162*)&aggl[base + 2] = lb;
}

// ---------------- input x -> bf16 hi/lo (+ fused aux gating) ----------------
#define NXBLK 12500      // NN*256/4/256
__global__ void xconv_kernel(const float* __restrict__ x, __nv_bfloat16* __restrict__ xh,
                             __nv_bfloat16* __restrict__ xl,
                             const float* __restrict__ nsa, const float* __restrict__ c,
                             const float* __restrict__ d, float* __restrict__ xaux) {
    if (blockIdx.x < NXBLK) {
        int i = blockIdx.x * 256 + threadIdx.x;
        float4 v = *(const float4*)&x[i * 4];
        __nv_bfloat16 h0, l0, h1, l1, h2, l2, h3, l3;
        split_bf16(v.x, h0, l0); split_bf16(v.y, h1, l1);
        split_bf16(v.z, h2, l2); split_bf16(v.w, h3, l3);
        __nv_bfloat162 ha, hb, la, lb;
        ha.x = h0; ha.y = h1; hb.x = h2; hb.y = h3;
        la.x = l0; la.y = l1; lb.x = l2; lb.y = l3;
        *(__nv_bfloat162*)&xh[i * 4]     = ha;
        *(__nv_bfloat162*)&xh[i * 4 + 2] = hb;
        *(__nv_bfloat162*)&xl[i * 4]     = la;
        *(__nv_bfloat162*)&xl[i * 4 + 2] = lb;
    } else {
        int i = (blockIdx.x - NXBLK) * 256 + threadIdx.x;
        if (i < NN) {
            float v = c[0] * nsa[i] - d[0];
            xaux[i] = 1.0f / (1.0f + __expf(-v));
        }
    }
}

// ---------------- weight transpose + split ----------------
struct WTab {
    const float* src[8];
    int K[8];
    int N[8];
    int off[8];
};
__global__ void wconv_kernel(WTab tb, __nv_bfloat16* __restrict__ wh,
                             __nv_bfloat16* __restrict__ wl) {
    int e = blockIdx.y;
    int i = blockIdx.x * 256 + threadIdx.x;
    int K = tb.K[e], N = tb.N[e];
    if (i >= K * N) return;
    int k = i / N, n = i - k * N;
    float w = tb.src[e][(size_t)k * N + n];
    __nv_bfloat16 h, l; split_bf16(w, h, l);
    size_t o = (size_t)tb.off[e] + (size_t)n * K + k;
    wh[o] = h; wl[o] = l;
}

// ---------------- HMMA GEMM: BM=128, X/Y chunk schedule, 3-stage pipeline -----
// type X (c < nkc): load Ah,Al,Bh -> Ah*Bh + Al*Bh (B regs reused)
// type Y (c >= nkc): load Ah,Bl   -> Ah*Bl
#define SM_STRIDE 80
#define TILE_B    10240
#define BUF_BYTES 30720
template<bool GELU, int OMODE>
__global__ void __launch_bounds__(256)
hmma_kernel(const __nv_bfloat16* __restrict__ Ah, const __nv_bfloat16* __restrict__ Al,
            const __nv_bfloat16* __restrict__ Bh, const __nv_bfloat16* __restrict__ Bl,
            float* __restrict__ C, __nv_bfloat16* __restrict__ Ch,
            __nv_bfloat16* __restrict__ Cl, const float* __restrict__ bias,
            int M, int K, int ldc,
            int zsA, int zsB, int zsC, int zsBias)
{
    extern __shared__ char smem[];
    const uint32_t sbase = smem_u32(smem);
    const int tid = threadIdx.x, lane = tid & 31, wid = tid >> 5;
    const int warp_m = wid & 3, warp_n = wid >> 2;
    const int row0 = blockIdx.y * 128;
    const int col0 = blockIdx.x * 128;
    const int z = blockIdx.z;
    Ah += (size_t)z * zsA; Al += (size_t)z * zsA;
    Bh += (size_t)z * zsB; Bl += (size_t)z * zsB;
    if (C)  C  += (size_t)z * zsC;
    if (Ch) { Ch += (size_t)z * zsC; Cl += (size_t)z * zsC; }
    if (bias) bias += (size_t)z * zsBias;
    const int KB = K * 2;
    const int nkc = K >> 5;
    const int T = 2 * nkc;

    float acc[2][8][4];
    #pragma unroll
    for (int i = 0; i < 2; ++i)
        #pragma unroll
        for (int j = 0; j < 8; ++j)
            #pragma unroll
            for (int k = 0; k < 4; ++k) acc[i][j][k] = 0.f;

    auto load = [&](int c, int b) {
        bool tx = c < nkc;
        int in = tx ? c : c - nkc;
        const char* A0 = (const char*)Ah + (size_t)row0 * KB + in * 64;
        const char* B0 = (const char*)(tx ? Bh : Bl) + (size_t)col0 * KB + in * 64;
        uint32_t s  = sbase + b * BUF_BYTES;
        uint32_t s1 = s + TILE_B;
        uint32_t sB = s + 2 * TILE_B;
        #pragma unroll
        for (int i = 0; i < 2; ++i) {
            int g = tid + i * 256;
            int r = g >> 2, ch = g & 3;
            uint32_t so = r * SM_STRIDE + ch * 16;
            size_t go = (size_t)r * KB + ch * 16;
            int sz = (row0 + r < M) ? 16 : 0;
            size_t goA = sz ? go : (size_t)(ch * 16);
            cp16(s + so, A0 + goA, sz);
            cp16(sB + so, B0 + go, 16);
        }
        if (tx) {
            const char* A1 = (const char*)Al + (size_t)row0 * KB + in * 64;
            #pragma unroll
            for (int i = 0; i < 2; ++i) {
                int g = tid + i * 256;
                int r = g >> 2, ch = g & 3;
                uint32_t so = r * SM_STRIDE + ch * 16;
                int sz = (row0 + r < M) ? 16 : 0;
                const char* ga = A1 + (size_t)(sz ? r : 0) * KB + ch * 16;
                cp16(s1 + so, ga, sz);
            }
        }
        asm volatile("cp.async.commit_group;" ::: "memory");
    };

    load(0, 0);
    if (T > 1) load(1, 1);

    for (int c = 0; c < T; ++c) {
        if (c + 2 < T) {
            load(c + 2, (c + 2) % 3);
            asm volatile("cp.async.wait_group 2;" ::: "memory");
        } else if (c + 1 < T) {
            asm volatile("cp.async.wait_group 1;" ::: "memory");
        } else {
            asm volatile("cp.async.wait_group 0;" ::: "memory");
        }
        __syncthreads();

        bool tx = c < nkc;
        uint32_t s  = sbase + (c % 3) * BUF_BYTES;
        uint32_t s1 = s + TILE_B;
        uint32_t sB = s + 2 * TILE_B;
        #pragma unroll
        for (int ks = 0; ks < 2; ++ks) {
            uint32_t bb[4][4];
            #pragma unroll
            for (int fb = 0; fb < 4; ++fb) {
                int rn = warp_n * 64 + fb * 16 + (lane & 7) + ((lane >> 4) << 3);
                uint32_t bd = sB + rn * SM_STRIDE + ks * 32 + (((lane >> 3) & 1) << 4);
                LDSM4(bb[fb], bd);
            }
            uint32_t a[2][4];
            #pragma unroll
            for (int fm = 0; fm < 2; ++fm) {
                int rr = warp_m * 32 + fm * 16 + (lane & 15);
                uint32_t ad = s + rr * SM_STRIDE + ks * 32 + ((lane >> 4) << 4);
                LDSM4(a[fm], ad);
            }
            #pragma unroll
            for (int fm = 0; fm < 2; ++fm)
                #pragma unroll
                for (int fb = 0; fb < 4; ++fb) {
                    mma16816(acc[fm][fb * 2],     a[fm], bb[fb][0], bb[fb][1]);
                    mma16816(acc[fm][fb * 2 + 1], a[fm], bb[fb][2], bb[fb][3]);
                }
            if (tx) {
                #pragma unroll
                for (int fm = 0; fm < 2; ++fm) {
                    int rr = warp_m * 32 + fm * 16 + (lane & 15);
                    uint32_t ad = s1 + rr * SM_STRIDE + ks * 32 + ((lane >> 4) << 4);
                    LDSM4(a[fm], ad);
                }
                #pragma unroll
                for (int fm = 0; fm < 2; ++fm)
                    #pragma unroll
                    for (int fb = 0; fb < 4; ++fb) {
                        mma16816(acc[fm][fb * 2],     a[fm], bb[fb][0], bb[fb][1]);
                        mma16816(acc[fm][fb * 2 + 1], a[fm], bb[fb][2], bb[fb][3]);
                    }
            }
        }
        __syncthreads();
    }

    // epilogue
    #pragma unroll
    for (int fm = 0; fm < 2; ++fm) {
        int rbase = row0 + warp_m * 32 + fm * 16 + (lane >> 2);
        #pragma unroll
        for (int half = 0; half < 2; ++half) {
            int r = rbase + half * 8;
            if (r >= M) continue;
            #pragma unroll
            for (int fn = 0; fn < 8; ++fn) {
                int cc = col0 + warp_n * 64 + fn * 8 + (lane & 3) * 2;
                float v0 = acc[fm][fn][half * 2];
                float v1 = acc[fm][fn][half * 2 + 1];
                if (bias) { v0 += bias[cc]; v1 += bias[cc + 1]; }
                if (GELU) { v0 = gelu_f(v0); v1 = gelu_f(v1); }
                size_t o = (size_t)r * ldc + cc;
                if (OMODE == 0 || OMODE == 2) {
                    float2 f2 = make_float2(v0, v1);
                    *(float2*)&C[o] = f2;
                }
                if (OMODE == 1 || OMODE == 2) {
                    __nv_bfloat16 h0, l0, h1, l1;
                    split_bf16(v0, h0, l0); split_bf16(v1, h1, l1);
                    __nv_bfloat162 hp, lp;
                    hp.x = h0; hp.y = h1; lp.x = l0; lp.y = l1;
                    *(__nv_bfloat162*)&Ch[o] = hp;
                    *(__nv_bfloat162*)&Cl[o] = lp;
                }
            }
        }
    }
}

// ---------------- host ----------------
static void* sym(const void* s) {
    void* p = nullptr;
    cudaGetSymbolAddress(&p, s);
    return p;
}

#define SMEM_HM (3 * BUF_BYTES)

extern "C" void kernel_launch(void* const* d_in, const int* in_sizes, int n_in,
                              void* d_out, int out_size) {
    const float* x      = (const float*)d_in[0];
    const int*   ei     = (const int*)  d_in[1];
    const float* nsa    = (const float*)d_in[2];
    const float* c_p    = (const float*)d_in[3];
    const float* d_p    = (const float*)d_in[4];
    const float* w_in   = (const float*)d_in[5];
    const float* b_in   = (const float*)d_in[6];
    const float* bn_g   = (const float*)d_in[7];
    const float* bn_b   = (const float*)d_in[8];
    const float* lin_l  = (const float*)d_in[9];
    const float* lin_r  = (const float*)d_in[10];
    const float* attb   = (const float*)d_in[11];
    const float* wcat   = (const float*)d_in[12];
    const float* ffw1   = (const float*)d_in[13];
    const float* ffb1   = (const float*)d_in[14];
    const float* ffw2   = (const float*)d_in[15];
    const float* ffb2   = (const float*)d_in[16];
    const float* wproj  = (const float*)d_in[17];
    const float* bproj  = (const float*)d_in[18];
    float* out = (float*)d_out;

    float* p_x4   = (float*)sym(g_x4);
    float* p_invn = (float*)sym(g_invn);
    float* p_xaux = (float*)sym(g_xaux);
    float* p_bvec = (float*)sym(g_bvec);
    float* p_bn   = (float*)sym(g_bnstat);
    float* p_bnb  = (float*)sym(g_bnb);
    float* p_pjb  = (float*)sym(g_pjb);
    int* p_din  = (int*)sym(g_deg_in);
    int* p_dout = (int*)sym(g_deg_out);
    int* p_oin  = (int*)sym(g_off_in);
    int* p_oout = (int*)sym(g_off_out);
    int* p_cin  = (int*)sym(g_cur_in);
    int* p_cout = (int*)sym(g_cur_out);
    int* p_colin  = (int*)sym(g_col_in);
    int* p_colout = (int*)sym(g_col_out);
    __nv_bfloat16* p_xh   = (__nv_bfloat16*)sym(g_xh);
    __nv_bfloat16* p_xlo  = (__nv_bfloat16*)sym(g_xlo);
    __nv_bfloat16* p_hh   = (__nv_bfloat16*)sym(g_hh);
    __nv_bfloat16* p_hl   = (__nv_bfloat16*)sym(g_hl);
    __nv_bfloat16* p_aggh = (__nv_bfloat16*)sym(g_aggh);
    __nv_bfloat16* p_aggl = (__nv_bfloat16*)sym(g_aggl);
    __nv_bfloat16* p_zh   = (__nv_bfloat16*)sym(g_zh);
    __nv_bfloat16* p_zl   = (__nv_bfloat16*)sym(g_zl);
    __nv_bfloat16* p_th   = (__nv_bfloat16*)sym(g_th);
    __nv_bfloat16* p_tl   = (__nv_bfloat16*)sym(g_tl);
    __nv_bfloat16* p_wth  = (__nv_bfloat16*)sym(g_wth);
    __nv_bfloat16* p_wtl  = (__nv_bfloat16*)sym(g_wtl);

    cudaFuncSetAttribute(hmma_kernel<false, 0>, cudaFuncAttributeMaxDynamicSharedMemorySize, SMEM_HM);
    cudaFuncSetAttribute(hmma_kernel<true,  1>, cudaFuncAttributeMaxDynamicSharedMemorySize, SMEM_HM);
    cudaFuncSetAttribute(hmma_kernel<false, 1>, cudaFuncAttributeMaxDynamicSharedMemorySize, SMEM_HM);

    const int MB = (NN + 127) / 128;   // 391
    dim3 g1(1, MB), g4(4, MB), gz(1, MB, 2);
    const int gatBlocks = (NN * 32 + 255) / 256;
    const int NNHD = NN * HD;

    // ---- operand conversions (+fused aux) ----
    xconv_kernel<<<NXBLK + (NN + 255) / 256, 256>>>(x, p_xh, p_xlo, nsa, c_p, d_p, p_xaux);
    WTab tb;
    int e = 0;
    tb.src[e] = w_in; tb.K[e] = 256; tb.N[e] = 128; tb.off[e] = OFF_WIN; ++e;
    for (int i = 0; i < 4; ++i) { tb.src[e] = wcat + (size_t)i * 16384; tb.K[e] = 128; tb.N[e] = 128; tb.off[e] = OFF_WC + i * 16384; ++e; }
    for (int i = 0; i < 2; ++i) { tb.src[e] = ffw1 + (size_t)i * 32768; tb.K[e] = 256; tb.N[e] = 128; tb.off[e] = OFF_F1 + i * 32768; ++e; }
    tb.src[e] = ffw2; tb.K[e] = 128; tb.N[e] = 128; tb.off[e] = OFF_F2; ++e;   // layer 0 only
    wconv_kernel<<<dim3(256, 8), 256>>>(tb, p_wth, p_wtl);

    // ---- input projection: hh/hl = x @ w_in + b_in ----
    hmma_kernel<false, 1><<<g1, 256, SMEM_HM>>>(p_xh, p_xlo, p_wth + OFF_WIN, p_wtl + OFF_WIN,
                                                nullptr, p_hh, p_hl, b_in, NN, 256, HD, 0, 0, 0, 0);

    // ---- folded final weights (independent) ----
    pjfold_kernel<<<258, 256>>>(ffw2, wproj, ffb2, bproj, p_wth, p_wtl, p_pjb);

    // ---- CSR build ----
    zero2_kernel<<<(NN + 255) / 256, 256>>>(p_din, p_dout, NN);
    hist_kernel<<<(EE + 255) / 256, 256>>>(ei, p_din, p_dout);
    scan2_kernel<<<2, 1024>>>(p_din, p_oin, p_cin, p_colin,
                              p_dout, p_oout, p_cout, p_colout);
    scatter_kernel<<<(EE + 255) / 256, 256>>>(ei, p_cin, p_colin, p_cout, p_colout);

    for (int l = 0; l < 2; ++l) {
        zero_float_kernel<<<1, 256>>>(p_bn, 256);
        bn_reduce_kernel<<<512, 128>>>(p_hh, p_hl, p_bn);
        bnfold_kernel<<<dim3(64, 6), 256>>>(lin_l, lin_r, p_bn, bn_g + l * HD, bn_b + l * HD,
                                            l, attb, wcat, p_wth, p_wtl, p_bnb, p_bvec);

        // fused projection: x4 = h @ W' + bnb  (N=512)
        hmma_kernel<false, 0><<<g4, 256, SMEM_HM>>>(p_hh, p_hl,
            p_wth + OFF_PROJ, p_wtl + OFF_PROJ,
            p_x4, nullptr, nullptr, p_bnb, NN, 128, 512, 0, 0, 0, 0);

        invnorm4_kernel<<<gatBlocks, 256>>>(p_x4, p_xaux, p_invn);

        gat_kernel<<<gatBlocks, 256>>>(p_oin, p_colin, p_x4, p_x4 + 128,
                                       p_invn + 0 * NN, p_invn + 1 * NN, p_aggh, p_aggl);
        gat_kernel<<<gatBlocks, 256>>>(p_oout, p_colout, p_x4 + 256, p_x4 + 384,
                                       p_invn + 2 * NN, p_invn + 3 * NN,
                                       p_aggh + NNHD, p_aggl + NNHD);

        int i0 = l * 2;
        // merged wcat pair: z=0 -> aggA@wc0 -> z cols [0:128); z=1 -> aggB@wc1 -> [128:256)
        hmma_kernel<true, 1><<<gz, 256, SMEM_HM>>>(p_aggh, p_aggl,
            p_wth + OFF_WC + i0 * 16384, p_wtl + OFF_WC + i0 * 16384,
            nullptr, p_zh, p_zl, p_bvec, NN, 128, 256,
            NNHD, 16384, 128, 128);

        hmma_kernel<true, 1><<<g1, 256, SMEM_HM>>>(p_zh, p_zl, p_wth + OFF_F1 + l * 32768,
            p_wtl + OFF_F1 + l * 32768, nullptr, p_th, p_tl, ffb1 + l * HD, NN, 256, HD, 0, 0, 0, 0);

        if (l == 0) {
            hmma_kernel<false, 1><<<g1, 256, SMEM_HM>>>(p_th, p_tl, p_wth + OFF_F2,
                p_wtl + OFF_F2, nullptr, p_hh, p_hl, ffb2, NN, 128, HD, 0, 0, 0, 0);
        } else {
            // folded ffn2(l1) + final projection -> d_out [NN, 512]
            hmma_kernel<false, 0><<<g4, 256, SMEM_HM>>>(p_th, p_tl, p_wth + OFF_PJ,
                p_wtl + OFF_PJ, out, nullptr, nullptr, p_pjb, NN, 128, 512, 0, 0, 0, 0);
        }
    }
}

// round 16
// speedup vs baseline: 1.2594x; 1.0158x over previous
#include <cuda_runtime.h>
#include <cuda_bf16.h>
#include <cstdint>
#include <math.h>

#define NN  50000
#define EE  800000
#define ET  850000
#define HD  128

// ---------------- weight-transpose offsets (elements) ----------------
#define OFF_WIN  0
#define OFF_PROJ 32768
#define OFF_WC   163840
#define OFF_F1   229376
#define OFF_F2   294912
#define OFF_PJ   327680
#define WTOT     393216

// ---------------- device scratch ----------------
__device__ float g_x4[NN*512];
__device__ float g_invn[4*NN];
__device__ float g_xaux[NN];
__device__ float g_bvec[256];
__device__ float g_bnstat[256];
__device__ float g_bnb[512];
__device__ float g_pjb[512];
__device__ int   g_deg_in[NN];
__device__ int   g_deg_out[NN];
__device__ int   g_off_in[NN+1];
__device__ int   g_off_out[NN+1];
__device__ int   g_cur_in[NN];
__device__ int   g_cur_out[NN];
__device__ int   g_col_in[ET];
__device__ int   g_col_out[ET];
__device__ __nv_bfloat16 g_xh [NN*256];
__device__ __nv_bfloat16 g_xlo[NN*256];
__device__ __nv_bfloat16 g_hh [NN*HD];
__device__ __nv_bfloat16 g_hl [NN*HD];
__device__ __nv_bfloat16 g_aggh[2*NN*HD];
__device__ __nv_bfloat16 g_aggl[2*NN*HD];
__device__ __nv_bfloat16 g_zh [NN*256];
__device__ __nv_bfloat16 g_zl [NN*256];
__device__ __nv_bfloat16 g_th [NN*HD];
__device__ __nv_bfloat16 g_tl [NN*HD];
__device__ __nv_bfloat16 g_wth[WTOT];
__device__ __nv_bfloat16 g_wtl[WTOT];

// ---------------- helpers ----------------
__device__ __forceinline__ uint32_t smem_u32(const void* p) {
    uint32_t a;
    asm("{ .reg .u64 t; cvta.to.shared.u64 t, %1; cvt.u32.u64 %0, t; }" : "=r"(a) : "l"(p));
    return a;
}
__device__ __forceinline__ void cp16(uint32_t s, const void* g, int sz) {
    asm volatile("cp.async.cg.shared.global [%0], [%1], 16, %2;"
                 :: "r"(s), "l"(g), "r"(sz));
}
#define LDSM4(R, addr) \
    asm volatile("ldmatrix.sync.aligned.m8n8.x4.shared.b16 {%0,%1,%2,%3}, [%4];" \
        : "=r"((R)[0]), "=r"((R)[1]), "=r"((R)[2]), "=r"((R)[3]) : "r"(addr))

__device__ __forceinline__ void mma16816(float* d, const uint32_t* a,
                                         uint32_t b0, uint32_t b1) {
    asm volatile("mma.sync.aligned.m16n8k16.row.col.f32.bf16.bf16.f32 "
        "{%0,%1,%2,%3}, {%4,%5,%6,%7}, {%8,%9}, {%0,%1,%2,%3};"
        : "+f"(d[0]), "+f"(d[1]), "+f"(d[2]), "+f"(d[3])
        : "r"(a[0]), "r"(a[1]), "r"(a[2]), "r"(a[3]), "r"(b0), "r"(b1));
}

__device__ __forceinline__ float gelu_f(float x) {
    return 0.5f * x * (1.0f + erff(x * 0.70710678118654752f));
}
__device__ __forceinline__ void split_bf16(float v, __nv_bfloat16& h, __nv_bfloat16& l) {
    h = __float2bfloat16(v);
    l = __float2bfloat16(v - __bfloat162float(h));
}

// ---------------- tiny utility kernels ----------------
__global__ void zero2_kernel(int* a, int* b, int n) {
    int i = blockIdx.x * blockDim.x + threadIdx.x;
    if (i < n) { a[i] = 0; b[i] = 0; }
}
__global__ void zero_float_kernel(float* p, int n) {
    int i = blockIdx.x * blockDim.x + threadIdx.x;
    if (i < n) p[i] = 0.0f;
}
__global__ void hist_kernel(const int* __restrict__ ei, int* __restrict__ din,
                            int* __restrict__ dout) {
    int e = blockIdx.x * blockDim.x + threadIdx.x;
    if (e >= EE) return;
    int s = ei[e];
    int d = ei[EE + e];
    atomicAdd(&dout[s], 1);
    atomicAdd(&din[d], 1);
}
__global__ void scan2_kernel(const int* __restrict__ degA, int* __restrict__ roffA,
                             int* __restrict__ curA, int* __restrict__ colA,
                             const int* __restrict__ degB, int* __restrict__ roffB,
                             int* __restrict__ curB, int* __restrict__ colB) {
    const int* deg  = blockIdx.x ? degB  : degA;
    int* roff       = blockIdx.x ? roffB : roffA;
    int* cursor     = blockIdx.x ? curB  : curA;
    int* colidx     = blockIdx.x ? colB  : colA;
    __shared__ int sh[1024];
    const int CH = (NN + 1023) / 1024;
    int t = threadIdx.x;
    int s0 = t * CH;
    int s1 = min(s0 + CH, NN);
    int sum = 0;
    for (int i = s0; i < s1; ++i) sum += deg[i] + 1;
    sh[t] = sum;
    __syncthreads();
    for (int off = 1; off < 1024; off <<= 1) {
        int v = (t >= off) ? sh[t - off] : 0;
        __syncthreads();
        sh[t] += v;
        __syncthreads();
    }
    int run = sh[t] - sum;
    if (t == 0) roff[0] = 0;
    for (int i = s0; i < s1; ++i) {
        int v = deg[i] + 1;
        colidx[run] = i;       // self loop first
        cursor[i] = run + 1;
        run += v;
        roff[i + 1] = run;
    }
}
__global__ void scatter_kernel(const int* __restrict__ ei, int* __restrict__ cin,
                               int* __restrict__ colin, int* __restrict__ cout,
                               int* __restrict__ colout) {
    int e = blockIdx.x * blockDim.x + threadIdx.x;
    if (e >= EE) return;
    int s = ei[e];
    int d = ei[EE + e];
    int p = atomicAdd(&cin[d], 1);  colin[p]  = s;
    int q = atomicAdd(&cout[s], 1); colout[q] = d;
}

// ---------------- batchnorm stats from bf16 hi/lo ----------------
__global__ void bn_reduce_kernel(const __nv_bfloat16* __restrict__ hh,
                                 const __nv_bfloat16* __restrict__ hl,
                                 float* __restrict__ stat) {
    int col = threadIdx.x;
    float s = 0.f, ss = 0.f;
    for (int r = blockIdx.x; r < NN; r += gridDim.x) {
        size_t o = (size_t)r * HD + col;
        float v = __bfloat162float(hh[o]) + __bfloat162float(hl[o]);
        s += v; ss += v * v;
    }
    atomicAdd(&stat[col], s);
    atomicAdd(&stat[128 + col], ss);
}

// ---------------- merged BN fold (weights + bias + bvec) ----------------
__global__ void bnfold_kernel(const float* __restrict__ lin_l, const float* __restrict__ lin_r,
                              const float* __restrict__ stat, const float* __restrict__ gamma,
                              const float* __restrict__ beta, int layer,
                              const float* __restrict__ attb, const float* __restrict__ wcat,
                              __nv_bfloat16* __restrict__ wh, __nv_bfloat16* __restrict__ wl,
                              float* __restrict__ bnb, float* __restrict__ bvec) {
    int y = blockIdx.y;
    const float invN = 1.0f / (float)NN;
    if (y < 4) {
        int e = y, d = e >> 1;
        const float* src = ((e & 1) ? lin_r : lin_l) + (size_t)(layer * 2 + d) * 16384;
        int i = blockIdx.x * 256 + threadIdx.x;
        int k = i >> 7, n = i & 127;
        float mu  = stat[k] * invN;
        float var = stat[128 + k] * invN - mu * mu;
        float s_k = gamma[k] * rsqrtf(var + 1e-5f);
        float w = src[(size_t)k * 128 + n] * s_k;
        __nv_bfloat16 h, l; split_bf16(w, h, l);
        size_t o = (size_t)OFF_PROJ + e * 16384 + (size_t)n * 128 + k;
        wh[o] = h; wl[o] = l;
    } else if (y == 4) {
        int n = blockIdx.x * 256 + threadIdx.x;
        if (n >= 512) return;
        int e = n >> 7, nn = n & 127;
        int d = e >> 1;
        const float* src = ((e & 1) ? lin_r : lin_l) + (size_t)(layer * 2 + d) * 16384;
        float acc = 0.f;
        for (int k = 0; k < 128; ++k) {
            float mu  = stat[k] * invN;
            float var = stat[128 + k] * invN - mu * mu;
            float s_k = gamma[k] * rsqrtf(var + 1e-5f);
            float t_k = beta[k] - mu * s_k;
            acc += t_k * src[(size_t)k * 128 + nn];
        }
        bnb[n] = acc;
    } else {
        if (blockIdx.x != 0) return;
        int tid = threadIdx.x;
        int dir = tid >> 7, t = tid & 127;
        const float* b = attb + (size_t)layer * 256 + dir * 128;
        const float* w = wcat + (size_t)layer * 2 * HD * HD + (size_t)dir * 128 * 128;
        float acc = 0.f;
        for (int k = 0; k < 128; ++k) acc += b[k] * w[k * 128 + t];
        bvec[tid] = acc;
    }
}

// ---------------- ffn2(l1)@wproj fold: block per k, coalesced over n2 --------
// blocks 0..127: k = blockIdx.x; each thread handles n2 = tid and tid+256.
// block 128: bias fold (512 outputs, 2 per thread).
__global__ void pjfold_kernel(const float* __restrict__ ffw2, const float* __restrict__ wproj,
                              const float* __restrict__ ffb2, const float* __restrict__ bproj,
                              __nv_bfloat16* __restrict__ wh, __nv_bfloat16* __restrict__ wl,
                              float* __restrict__ pjb) {
    __shared__ float w2s[128];
    int tid = threadIdx.x;
    if (blockIdx.x < 128) {
        int k = blockIdx.x;
        if (tid < 128) w2s[tid] = ffw2[(size_t)16384 + (size_t)k * 128 + tid]; // layer 1
        __syncthreads();
        #pragma unroll
        for (int h = 0; h < 2; ++h) {
            int n2 = tid + h * 256;
            float acc = 0.f;
            #pragma unroll 8
            for (int m = 0; m < 128; ++m) acc += w2s[m] * wproj[(size_t)m * 512 + n2];
            __nv_bfloat16 hh, ll; split_bf16(acc, hh, ll);
            size_t o = (size_t)OFF_PJ + (size_t)n2 * 128 + k;
            wh[o] = hh; wl[o] = ll;
        }
    } else {
        if (tid < 128) w2s[tid] = ffb2[128 + tid];  // layer-1 bias
        __syncthreads();
        #pragma unroll
        for (int h = 0; h < 2; ++h) {
            int n2 = tid + h * 256;
            float acc = bproj[n2];
            #pragma unroll 8
            for (int m = 0; m < 128; ++m) acc += w2s[m] * wproj[(size_t)m * 512 + n2];
            pjb[n2] = acc;
        }
    }
}

// ---------------- fused 4-section inverse-norm (+gate fold) ----------------
__global__ void invnorm4_kernel(const float* __restrict__ x4, const float* __restrict__ xaux,
                                float* __restrict__ invn) {
    int w = (blockIdx.x * blockDim.x + threadIdx.x) >> 5;
    int lane = threadIdx.x & 31;
    if (w >= NN) return;
    const float* row = x4 + (size_t)w * 512;
    float ss[4];
    #pragma unroll
    for (int s = 0; s < 4; ++s) {
        float4 v = *(const float4*)&row[s * 128 + lane * 4];
        ss[s] = v.x * v.x + v.y * v.y + v.z * v.z + v.w * v.w;
    }
    #pragma unroll
    for (int off = 16; off > 0; off >>= 1) {
        ss[0] += __shfl_xor_sync(0xffffffffu, ss[0], off);
        ss[1] += __shfl_xor_sync(0xffffffffu, ss[1], off);
        ss[2] += __shfl_xor_sync(0xffffffffu, ss[2], off);
        ss[3] += __shfl_xor_sync(0xffffffffu, ss[3], off);
    }
    if (lane == 0) {
        float gw = xaux[w] * 4.0f;
        invn[0 * NN + w] = gw / fmaxf(sqrtf(ss[0]), 1e-12f);
        invn[1 * NN + w] = 1.0f / fmaxf(sqrtf(ss[1]), 1e-12f);
        invn[2 * NN + w] = gw / fmaxf(sqrtf(ss[2]), 1e-12f);
        invn[3 * NN + w] = 1.0f / fmaxf(sqrtf(ss[3]), 1e-12f);
    }
}

// ---------------- GAT-COS aggregation (warp per node, unroll x4) -------------
__global__ void gat_kernel(const int* __restrict__ roff, const int* __restrict__ col,
                           const float* __restrict__ xl, const float* __restrict__ xr,
                           const float* __restrict__ gwl, const float* __restrict__ invr,
                           __nv_bfloat16* __restrict__ aggh, __nv_bfloat16* __restrict__ aggl) {
    const int LD = 512;
    int w = (blockIdx.x * blockDim.x + threadIdx.x) >> 5;
    int lane = threadIdx.x & 31;
    if (w >= NN) return;
    float inr = invr[w];
    float4 xri = *(const float4*)&xr[(size_t)w * LD + lane * 4];
    float4 nr = make_float4(xri.x * inr, xri.y * inr, xri.z * inr, xri.w * inr);
    float s = 0.f;
    float4 acc = make_float4(0.f, 0.f, 0.f, 0.f);
    int e = roff[w], e1 = roff[w + 1];
    for (; e + 4 <= e1; e += 4) {
        int j0 = col[e], j1 = col[e + 1], j2 = col[e + 2], j3 = col[e + 3];
        float4 x0 = *(const float4*)&xl[(size_t)j0 * LD + lane * 4];
        float4 x1 = *(const float4*)&xl[(size_t)j1 * LD + lane * 4];
        float4 x2 = *(const float4*)&xl[(size_t)j2 * LD + lane * 4];
        float4 x3 = *(const float4*)&xl[(size_t)j3 * LD + lane * 4];
        float g0 = gwl[j0], g1 = gwl[j1], g2 = gwl[j2], g3 = gwl[j3];
        float p0 = nr.x * x0.x + nr.y * x0.y + nr.z * x0.z + nr.w * x0.w;
        float p1 = nr.x * x1.x + nr.y * x1.y + nr.z * x1.z + nr.w * x1.w;
        float p2 = nr.x * x2.x + nr.y * x2.y + nr.z * x2.z + nr.w * x2.w;
        float p3 = nr.x * x3.x + nr.y * x3.y + nr.z * x3.z + nr.w * x3.w;
        #pragma unroll
        for (int off = 16; off > 0; off >>= 1) {
            p0 += __shfl_xor_sync(0xffffffffu, p0, off);
            p1 += __shfl_xor_sync(0xffffffffu, p1, off);
            p2 += __shfl_xor_sync(0xffffffffu, p2, off);
            p3 += __shfl_xor_sync(0xffffffffu, p3, off);
        }
        float q0 = __expf(g0 * fabsf(p0));
        float q1 = __expf(g1 * fabsf(p1));
        float q2 = __expf(g2 * fabsf(p2));
        float q3 = __expf(g3 * fabsf(p3));
        s += (q0 + q1) + (q2 + q3);
        acc.x += q0 * x0.x + q1 * x1.x + q2 * x2.x + q3 * x3.x;
        acc.y += q0 * x0.y + q1 * x1.y + q2 * x2.y + q3 * x3.y;
        acc.z += q0 * x0.z + q1 * x1.z + q2 * x2.z + q3 * x3.z;
        acc.w += q0 * x0.w + q1 * x1.w + q2 * x2.w + q3 * x3.w;
    }
    for (; e < e1; ++e) {
        int j0 = col[e];
        float4 x0 = *(const float4*)&xl[(size_t)j0 * LD + lane * 4];
        float g0 = gwl[j0];
        float p0 = nr.x * x0.x + nr.y * x0.y + nr.z * x0.z + nr.w * x0.w;
        #pragma unroll
        for (int off = 16; off > 0; off >>= 1)
            p0 += __shfl_xor_sync(0xffffffffu, p0, off);
        float q0 = __expf(g0 * fabsf(p0));
        s += q0;
        acc.x += q0 * x0.x; acc.y += q0 * x0.y;
        acc.z += q0 * x0.z; acc.w += q0 * x0.w;
    }
    float is = 1.0f / s;
    float o[4] = {acc.x * is, acc.y * is, acc.z * is, acc.w * is};
    size_t base = (size_t)w * HD + lane * 4;
    __nv_bfloat16 h0, l0, h1, l1, h2, l2, h3, l3;
    split_bf16(o[0], h0, l0); split_bf16(o[1], h1, l1);
    split_bf16(o[2], h2, l2); split_bf16(o[3], h3, l3);
    __nv_bfloat162 ha, hb, la, lb;
    ha.x = h0; ha.y = h1; hb.x = h2; hb.y = h3;
    la.x = l0; la.y = l1; lb.x = l2; lb.y = l3;
    *(__nv_bfloat162*)&aggh[base]     = ha;
    *(__nv_bfloat162*)&aggh[base + 2] = hb;
    *(__nv_bfloat162*)&aggl[base]     = la;
    *(__nv_bfloat162*)&aggl[base + 2] = lb;
}

// ---------------- input x -> bf16 hi/lo (+ fused aux gating) ----------------
#define NXBLK 12500
__global__ void xconv_kernel(const float* __restrict__ x, __nv_bfloat16* __restrict__ xh,
                             __nv_bfloat16* __restrict__ xl,
                             const float* __restrict__ nsa, const float* __restrict__ c,
                             const float* __restrict__ d, float* __restrict__ xaux) {
    if (blockIdx.x < NXBLK) {
        int i = blockIdx.x * 256 + threadIdx.x;
        float4 v = *(const float4*)&x[i * 4];
        __nv_bfloat16 h0, l0, h1, l1, h2, l2, h3, l3;
        split_bf16(v.x, h0, l0); split_bf16(v.y, h1, l1);
        split_bf16(v.z, h2, l2); split_bf16(v.w, h3, l3);
        __nv_bfloat162 ha, hb, la, lb;
        ha.x = h0; ha.y = h1; hb.x = h2; hb.y = h3;
        la.x = l0; la.y = l1; lb.x = l2; lb.y = l3;
        *(__nv_bfloat162*)&xh[i * 4]     = ha;
        *(__nv_bfloat162*)&xh[i * 4 + 2] = hb;
        *(__nv_bfloat162*)&xl[i * 4]     = la;
        *(__nv_bfloat162*)&xl[i * 4 + 2] = lb;
    } else {
        int i = (blockIdx.x - NXBLK) * 256 + threadIdx.x;
        if (i < NN) {
            float v = c[0] * nsa[i] - d[0];
            xaux[i] = 1.0f / (1.0f + __expf(-v));
        }
    }
}

// ---------------- weight transpose + split ----------------
struct WTab {
    const float* src[8];
    int K[8];
    int N[8];
    int off[8];
};
__global__ void wconv_kernel(WTab tb, __nv_bfloat16* __restrict__ wh,
                             __nv_bfloat16* __restrict__ wl) {
    int e = blockIdx.y;
    int i = blockIdx.x * 256 + threadIdx.x;
    int K = tb.K[e], N = tb.N[e];
    if (i >= K * N) return;
    int k = i / N, n = i - k * N;
    float w = tb.src[e][(size_t)k * N + n];
    __nv_bfloat16 h, l; split_bf16(w, h, l);
    size_t o = (size_t)tb.off[e] + (size_t)n * K + k;
    wh[o] = h; wl[o] = l;
}

// ---------------- HMMA GEMM: BM=128, X/Y chunk schedule, 3-stage pipeline -----
#define SM_STRIDE 80
#define TILE_B    10240
#define BUF_BYTES 30720
template<bool GELU, int OMODE>
__global__ void __launch_bounds__(256)
hmma_kernel(const __nv_bfloat16* __restrict__ Ah, const __nv_bfloat16* __restrict__ Al,
            const __nv_bfloat16* __restrict__ Bh, const __nv_bfloat16* __restrict__ Bl,
            float* __restrict__ C, __nv_bfloat16* __restrict__ Ch,
            __nv_bfloat16* __restrict__ Cl, const float* __restrict__ bias,
            int M, int K, int ldc,
            int zsA, int zsB, int zsC, int zsBias)
{
    extern __shared__ char smem[];
    const uint32_t sbase = smem_u32(smem);
    const int tid = threadIdx.x, lane = tid & 31, wid = tid >> 5;
    const int warp_m = wid & 3, warp_n = wid >> 2;
    const int row0 = blockIdx.y * 128;
    const int col0 = blockIdx.x * 128;
    const int z = blockIdx.z;
    Ah += (size_t)z * zsA; Al += (size_t)z * zsA;
    Bh += (size_t)z * zsB; Bl += (size_t)z * zsB;
    if (C)  C  += (size_t)z * zsC;
    if (Ch) { Ch += (size_t)z * zsC; Cl += (size_t)z * zsC; }
    if (bias) bias += (size_t)z * zsBias;
    const int KB = K * 2;
    const int nkc = K >> 5;
    const int T = 2 * nkc;

    float acc[2][8][4];
    #pragma unroll
    for (int i = 0; i < 2; ++i)
        #pragma unroll
        for (int j = 0; j < 8; ++j)
            #pragma unroll
            for (int k = 0; k < 4; ++k) acc[i][j][k] = 0.f;

    auto load = [&](int c, int b) {
        bool tx = c < nkc;
        int in = tx ? c : c - nkc;
        const char* A0 = (const char*)Ah + (size_t)row0 * KB + in * 64;
        const char* B0 = (const char*)(tx ? Bh : Bl) + (size_t)col0 * KB + in * 64;
        uint32_t s  = sbase + b * BUF_BYTES;
        uint32_t s1 = s + TILE_B;
        uint32_t sB = s + 2 * TILE_B;
        #pragma unroll
        for (int i = 0; i < 2; ++i) {
            int g = tid + i * 256;
            int r = g >> 2, ch = g & 3;
            uint32_t so = r * SM_STRIDE + ch * 16;
            size_t go = (size_t)r * KB + ch * 16;
            int sz = (row0 + r < M) ? 16 : 0;
            size_t goA = sz ? go : (size_t)(ch * 16);
            cp16(s + so, A0 + goA, sz);
            cp16(sB + so, B0 + go, 16);
        }
        if (tx) {
            const char* A1 = (const char*)Al + (size_t)row0 * KB + in * 64;
            #pragma unroll
            for (int i = 0; i < 2; ++i) {
                int g = tid + i * 256;
                int r = g >> 2, ch = g & 3;
                uint32_t so = r * SM_STRIDE + ch * 16;
                int sz = (row0 + r < M) ? 16 : 0;
                const char* ga = A1 + (size_t)(sz ? r : 0) * KB + ch * 16;
                cp16(s1 + so, ga, sz);
            }
        }
        asm volatile("cp.async.commit_group;" ::: "memory");
    };

    load(0, 0);
    if (T > 1) load(1, 1);

    for (int c = 0; c < T; ++c) {
        if (c + 2 < T) {
            load(c + 2, (c + 2) % 3);
            asm volatile("cp.async.wait_group 2;" ::: "memory");
        } else if (c + 1 < T) {
            asm volatile("cp.async.wait_group 1;" ::: "memory");
        } else {
            asm volatile("cp.async.wait_group 0;" ::: "memory");
        }
        __syncthreads();

        bool tx = c < nkc;
        uint32_t s  = sbase + (c % 3) * BUF_BYTES;
        uint32_t s1 = s + TILE_B;
        uint32_t sB = s + 2 * TILE_B;
        #pragma unroll
        for (int ks = 0; ks < 2; ++ks) {
            uint32_t bb[4][4];
            #pragma unroll
            for (int fb = 0; fb < 4; ++fb) {
                int rn = warp_n * 64 + fb * 16 + (lane & 7) + ((lane >> 4) << 3);
                uint32_t bd = sB + rn * SM_STRIDE + ks * 32 + (((lane >> 3) & 1) << 4);
                LDSM4(bb[fb], bd);
            }
            uint32_t a[2][4];
            #pragma unroll
            for (int fm = 0; fm < 2; ++fm) {
                int rr = warp_m * 32 + fm * 16 + (lane & 15);
                uint32_t ad = s + rr * SM_STRIDE + ks * 32 + ((lane >> 4) << 4);
                LDSM4(a[fm], ad);
            }
            #pragma unroll
            for (int fm = 0; fm < 2; ++fm)
                #pragma unroll
                for (int fb = 0; fb < 4; ++fb) {
                    mma16816(acc[fm][fb * 2],     a[fm], bb[fb][0], bb[fb][1]);
                    mma16816(acc[fm][fb * 2 + 1], a[fm], bb[fb][2], bb[fb][3]);
                }
            if (tx) {
                #pragma unroll
                for (int fm = 0; fm < 2; ++fm) {
                    int rr = warp_m * 32 + fm * 16 + (lane & 15);
                    uint32_t ad = s1 + rr * SM_STRIDE + ks * 32 + ((lane >> 4) << 4);
                    LDSM4(a[fm], ad);
                }
                #pragma unroll
                for (int fm = 0; fm < 2; ++fm)
                    #pragma unroll
                    for (int fb = 0; fb < 4; ++fb) {
                        mma16816(acc[fm][fb * 2],     a[fm], bb[fb][0], bb[fb][1]);
                        mma16816(acc[fm][fb * 2 + 1], a[fm], bb[fb][2], bb[fb][3]);
                    }
            }
        }
        __syncthreads();
    }

    // epilogue
    #pragma unroll
    for (int fm = 0; fm < 2; ++fm) {
        int rbase = row0 + warp_m * 32 + fm * 16 + (lane >> 2);
        #pragma unroll
        for (int half = 0; half < 2; ++half) {
            int r = rbase + half * 8;
            if (r >= M) continue;
            #pragma unroll
            for (int fn = 0; fn < 8; ++fn) {
                int cc = col0 + warp_n * 64 + fn * 8 + (lane & 3) * 2;
                float v0 = acc[fm][fn][half * 2];
                float v1 = acc[fm][fn][half * 2 + 1];
                if (bias) { v0 += bias[cc]; v1 += bias[cc + 1]; }
                if (GELU) { v0 = gelu_f(v0); v1 = gelu_f(v1); }
                size_t o = (size_t)r * ldc + cc;
                if (OMODE == 0 || OMODE == 2) {
                    float2 f2 = make_float2(v0, v1);
                    *(float2*)&C[o] = f2;
                }
                if (OMODE == 1 || OMODE == 2) {
                    __nv_bfloat16 h0, l0, h1, l1;
                    split_bf16(v0, h0, l0); split_bf16(v1, h1, l1);
                    __nv_bfloat162 hp, lp;
                    hp.x = h0; hp.y = h1; lp.x = l0; lp.y = l1;
                    *(__nv_bfloat162*)&Ch[o] = hp;
                    *(__nv_bfloat162*)&Cl[o] = lp;
                }
            }
        }
    }
}

// ---------------- host ----------------
static void* sym(const void* s) {
    void* p = nullptr;
    cudaGetSymbolAddress(&p, s);
    return p;
}

#define SMEM_HM (3 * BUF_BYTES)

extern "C" void kernel_launch(void* const* d_in, const int* in_sizes, int n_in,
                              void* d_out, int out_size) {
    const float* x      = (const float*)d_in[0];
    const int*   ei     = (const int*)  d_in[1];
    const float* nsa    = (const float*)d_in[2];
    const float* c_p    = (const float*)d_in[3];
    const float* d_p    = (const float*)d_in[4];
    const float* w_in   = (const float*)d_in[5];
    const float* b_in   = (const float*)d_in[6];
    const float* bn_g   = (const float*)d_in[7];
    const float* bn_b   = (const float*)d_in[8];
    const float* lin_l  = (const float*)d_in[9];
    const float* lin_r  = (const float*)d_in[10];
    const float* attb   = (const float*)d_in[11];
    const float* wcat   = (const float*)d_in[12];
    const float* ffw1   = (const float*)d_in[13];
    const float* ffb1   = (const float*)d_in[14];
    const float* ffw2   = (const float*)d_in[15];
    const float* ffb2   = (const float*)d_in[16];
    const float* wproj  = (const float*)d_in[17];
    const float* bproj  = (const float*)d_in[18];
    float* out = (float*)d_out;

    float* p_x4   = (float*)sym(g_x4);
    float* p_invn = (float*)sym(g_invn);
    float* p_xaux = (float*)sym(g_xaux);
    float* p_bvec = (float*)sym(g_bvec);
    float* p_bn   = (float*)sym(g_bnstat);
    float* p_bnb  = (float*)sym(g_bnb);
    float* p_pjb  = (float*)sym(g_pjb);
    int* p_din  = (int*)sym(g_deg_in);
    int* p_dout = (int*)sym(g_deg_out);
    int* p_oin  = (int*)sym(g_off_in);
    int* p_oout = (int*)sym(g_off_out);
    int* p_cin  = (int*)sym(g_cur_in);
    int* p_cout = (int*)sym(g_cur_out);
    int* p_colin  = (int*)sym(g_col_in);
    int* p_colout = (int*)sym(g_col_out);
    __nv_bfloat16* p_xh   = (__nv_bfloat16*)sym(g_xh);
    __nv_bfloat16* p_xlo  = (__nv_bfloat16*)sym(g_xlo);
    __nv_bfloat16* p_hh   = (__nv_bfloat16*)sym(g_hh);
    __nv_bfloat16* p_hl   = (__nv_bfloat16*)sym(g_hl);
    __nv_bfloat16* p_aggh = (__nv_bfloat16*)sym(g_aggh);
    __nv_bfloat16* p_aggl = (__nv_bfloat16*)sym(g_aggl);
    __nv_bfloat16* p_zh   = (__nv_bfloat16*)sym(g_zh);
    __nv_bfloat16* p_zl   = (__nv_bfloat16*)sym(g_zl);
    __nv_bfloat16* p_th   = (__nv_bfloat16*)sym(g_th);
    __nv_bfloat16* p_tl   = (__nv_bfloat16*)sym(g_tl);
    __nv_bfloat16* p_wth  = (__nv_bfloat16*)sym(g_wth);
    __nv_bfloat16* p_wtl  = (__nv_bfloat16*)sym(g_wtl);

    cudaFuncSetAttribute(hmma_kernel<false, 0>, cudaFuncAttributeMaxDynamicSharedMemorySize, SMEM_HM);
    cudaFuncSetAttribute(hmma_kernel<true,  1>, cudaFuncAttributeMaxDynamicSharedMemorySize, SMEM_HM);
    cudaFuncSetAttribute(hmma_kernel<false, 1>, cudaFuncAttributeMaxDynamicSharedMemorySize, SMEM_HM);

    const int MB = (NN + 127) / 128;   // 391
    dim3 g1(1, MB), g4(4, MB), gz(1, MB, 2);
    const int gatBlocks = (NN * 32 + 255) / 256;
    const int NNHD = NN * HD;

    // ---- operand conversions (+fused aux) ----
    xconv_kernel<<<NXBLK + (NN + 255) / 256, 256>>>(x, p_xh, p_xlo, nsa, c_p, d_p, p_xaux);
    WTab tb;
    int e = 0;
    tb.src[e] = w_in; tb.K[e] = 256; tb.N[e] = 128; tb.off[e] = OFF_WIN; ++e;
    for (int i = 0; i < 4; ++i) { tb.src[e] = wcat + (size_t)i * 16384; tb.K[e] = 128; tb.N[e] = 128; tb.off[e] = OFF_WC + i * 16384; ++e; }
    for (int i = 0; i < 2; ++i) { tb.src[e] = ffw1 + (size_t)i * 32768; tb.K[e] = 256; tb.N[e] = 128; tb.off[e] = OFF_F1 + i * 32768; ++e; }
    tb.src[e] = ffw2; tb.K[e] = 128; tb.N[e] = 128; tb.off[e] = OFF_F2; ++e;   // layer 0 only
    wconv_kernel<<<dim3(256, 8), 256>>>(tb, p_wth, p_wtl);

    // ---- input projection: hh/hl = x @ w_in + b_in ----
    hmma_kernel<false, 1><<<g1, 256, SMEM_HM>>>(p_xh, p_xlo, p_wth + OFF_WIN, p_wtl + OFF_WIN,
                                                nullptr, p_hh, p_hl, b_in, NN, 256, HD, 0, 0, 0, 0);

    // ---- folded final weights (independent) ----
    pjfold_kernel<<<129, 256>>>(ffw2, wproj, ffb2, bproj, p_wth, p_wtl, p_pjb);

    // ---- CSR build ----
    zero2_kernel<<<(NN + 255) / 256, 256>>>(p_din, p_dout, NN);
    hist_kernel<<<(EE + 255) / 256, 256>>>(ei, p_din, p_dout);
    scan2_kernel<<<2, 1024>>>(p_din, p_oin, p_cin, p_colin,
                              p_dout, p_oout, p_cout, p_colout);
    scatter_kernel<<<(EE + 255) / 256, 256>>>(ei, p_cin, p_colin, p_cout, p_colout);

    for (int l = 0; l < 2; ++l) {
        zero_float_kernel<<<1, 256>>>(p_bn, 256);
        bn_reduce_kernel<<<512, 128>>>(p_hh, p_hl, p_bn);
        bnfold_kernel<<<dim3(64, 6), 256>>>(lin_l, lin_r, p_bn, bn_g + l * HD, bn_b + l * HD,
                                            l, attb, wcat, p_wth, p_wtl, p_bnb, p_bvec);

        // fused projection: x4 = h @ W' + bnb  (N=512)
        hmma_kernel<false, 0><<<g4, 256, SMEM_HM>>>(p_hh, p_hl,
            p_wth + OFF_PROJ, p_wtl + OFF_PROJ,
            p_x4, nullptr, nullptr, p_bnb, NN, 128, 512, 0, 0, 0, 0);

        invnorm4_kernel<<<gatBlocks, 256>>>(p_x4, p_xaux, p_invn);

        gat_kernel<<<gatBlocks, 256>>>(p_oin, p_colin, p_x4, p_x4 + 128,
                                       p_invn + 0 * NN, p_invn + 1 * NN, p_aggh, p_aggl);
        gat_kernel<<<gatBlocks, 256>>>(p_oout, p_colout, p_x4 + 256, p_x4 + 384,
                                       p_invn + 2 * NN, p_invn + 3 * NN,
                                       p_aggh + NNHD, p_aggl + NNHD);

        int i0 = l * 2;
        // merged wcat pair: z=0 -> aggA@wc0 -> z cols [0:128); z=1 -> aggB@wc1 -> [128:256)
        hmma_kernel<true, 1><<<gz, 256, SMEM_HM>>>(p_aggh, p_aggl,
            p_wth + OFF_WC + i0 * 16384, p_wtl + OFF_WC + i0 * 16384,
            nullptr, p_zh, p_zl, p_bvec, NN, 128, 256,
            NNHD, 16384, 128, 128);

        hmma_kernel<true, 1><<<g1, 256, SMEM_HM>>>(p_zh, p_zl, p_wth + OFF_F1 + l * 32768,
            p_wtl + OFF_F1 + l * 32768, nullptr, p_th, p_tl, ffb1 + l * HD, NN, 256, HD, 0, 0, 0, 0);

        if (l == 0) {
            hmma_kernel<false, 1><<<g1, 256, SMEM_HM>>>(p_th, p_tl, p_wth + OFF_F2,
                p_wtl + OFF_F2, nullptr, p_hh, p_hl, ffb2, NN, 128, HD, 0, 0, 0, 0);
        } else {
            // folded ffn2(l1) + final projection -> d_out [NN, 512]
            hmma_kernel<false, 0><<<g4, 256, SMEM_HM>>>(p_th, p_tl, p_wth + OFF_PJ,
                p_wtl + OFF_PJ, out, nullptr, nullptr, p_pjb, NN, 128, 512, 0, 0, 0, 0);
        }
    }
}

// round 17
// speedup vs baseline: 1.2680x; 1.0069x over previous
#include <cuda_runtime.h>
#include <cuda_bf16.h>
#include <cstdint>
#include <math.h>

#define NN  50000
#define EE  800000
#define ET  850000
#define HD  128

// ---------------- weight-transpose offsets (elements) ----------------
#define OFF_WIN  0
#define OFF_PROJ 32768
#define OFF_WC   163840
#define OFF_F1   229376
#define OFF_F2   294912
#define OFF_PJ   327680
#define WTOT     393216

// ---------------- device scratch ----------------
__device__ float g_x4[NN*512];
__device__ float g_invn[4*NN];
__device__ float g_xaux[NN];
__device__ float g_bvec[256];
__device__ float g_bnstat[256];
__device__ float g_bnb[512];
__device__ float g_pjb[512];
__device__ int   g_deg_in[NN];
__device__ int   g_deg_out[NN];
__device__ int   g_off_in[NN+1];
__device__ int   g_off_out[NN+1];
__device__ int   g_cur_in[NN];
__device__ int   g_cur_out[NN];
__device__ int   g_col_in[ET];
__device__ int   g_col_out[ET];
__device__ __nv_bfloat16 g_xh [NN*256];
__device__ __nv_bfloat16 g_xlo[NN*256];
__device__ __nv_bfloat16 g_hh [NN*HD];
__device__ __nv_bfloat16 g_hl [NN*HD];
__device__ __nv_bfloat16 g_aggh[2*NN*HD];
__device__ __nv_bfloat16 g_aggl[2*NN*HD];
__device__ __nv_bfloat16 g_zh [NN*256];
__device__ __nv_bfloat16 g_zl [NN*256];
__device__ __nv_bfloat16 g_th [NN*HD];
__device__ __nv_bfloat16 g_tl [NN*HD];
__device__ __nv_bfloat16 g_wth[WTOT];
__device__ __nv_bfloat16 g_wtl[WTOT];

// ---------------- helpers ----------------
__device__ __forceinline__ uint32_t smem_u32(const void* p) {
    uint32_t a;
    asm("{ .reg .u64 t; cvta.to.shared.u64 t, %1; cvt.u32.u64 %0, t; }" : "=r"(a) : "l"(p));
    return a;
}
__device__ __forceinline__ void cp16(uint32_t s, const void* g, int sz) {
    asm volatile("cp.async.cg.shared.global [%0], [%1], 16, %2;"
                 :: "r"(s), "l"(g), "r"(sz));
}
#define LDSM4(R, addr) \
    asm volatile("ldmatrix.sync.aligned.m8n8.x4.shared.b16 {%0,%1,%2,%3}, [%4];" \
        : "=r"((R)[0]), "=r"((R)[1]), "=r"((R)[2]), "=r"((R)[3]) : "r"(addr))

__device__ __forceinline__ void mma16816(float* d, const uint32_t* a,
                                         uint32_t b0, uint32_t b1) {
    asm volatile("mma.sync.aligned.m16n8k16.row.col.f32.bf16.bf16.f32 "
        "{%0,%1,%2,%3}, {%4,%5,%6,%7}, {%8,%9}, {%0,%1,%2,%3};"
        : "+f"(d[0]), "+f"(d[1]), "+f"(d[2]), "+f"(d[3])
        : "r"(a[0]), "r"(a[1]), "r"(a[2]), "r"(a[3]), "r"(b0), "r"(b1));
}

__device__ __forceinline__ float gelu_f(float x) {
    return 0.5f * x * (1.0f + erff(x * 0.70710678118654752f));
}
__device__ __forceinline__ void split_bf16(float v, __nv_bfloat16& h, __nv_bfloat16& l) {
    h = __float2bfloat16(v);
    l = __float2bfloat16(v - __bfloat162float(h));
}

// ---------------- tiny utility kernels ----------------
__global__ void zero2_kernel(int* a, int* b, int n) {
    int i = blockIdx.x * blockDim.x + threadIdx.x;
    if (i < n) { a[i] = 0; b[i] = 0; }
}
__global__ void zero_float_kernel(float* p, int n) {
    int i = blockIdx.x * blockDim.x + threadIdx.x;
    if (i < n) p[i] = 0.0f;
}
__global__ void hist_kernel(const int* __restrict__ ei, int* __restrict__ din,
                            int* __restrict__ dout) {
    int e = blockIdx.x * blockDim.x + threadIdx.x;
    if (e >= EE) return;
    int s = ei[e];
    int d = ei[EE + e];
    atomicAdd(&dout[s], 1);
    atomicAdd(&din[d], 1);
}
__global__ void scan2_kernel(const int* __restrict__ degA, int* __restrict__ roffA,
                             int* __restrict__ curA, int* __restrict__ colA,
                             const int* __restrict__ degB, int* __restrict__ roffB,
                             int* __restrict__ curB, int* __restrict__ colB) {
    const int* deg  = blockIdx.x ? degB  : degA;
    int* roff       = blockIdx.x ? roffB : roffA;
    int* cursor     = blockIdx.x ? curB  : curA;
    int* colidx     = blockIdx.x ? colB  : colA;
    __shared__ int sh[1024];
    const int CH = (NN + 1023) / 1024;
    int t = threadIdx.x;
    int s0 = t * CH;
    int s1 = min(s0 + CH, NN);
    int sum = 0;
    for (int i = s0; i < s1; ++i) sum += deg[i] + 1;
    sh[t] = sum;
    __syncthreads();
    for (int off = 1; off < 1024; off <<= 1) {
        int v = (t >= off) ? sh[t - off] : 0;
        __syncthreads();
        sh[t] += v;
        __syncthreads();
    }
    int run = sh[t] - sum;
    if (t == 0) roff[0] = 0;
    for (int i = s0; i < s1; ++i) {
        int v = deg[i] + 1;
        colidx[run] = i;       // self loop first
        cursor[i] = run + 1;
        run += v;
        roff[i + 1] = run;
    }
}
__global__ void scatter_kernel(const int* __restrict__ ei, int* __restrict__ cin,
                               int* __restrict__ colin, int* __restrict__ cout,
                               int* __restrict__ colout) {
    int e = blockIdx.x * blockDim.x + threadIdx.x;
    if (e >= EE) return;
    int s = ei[e];
    int d = ei[EE + e];
    int p = atomicAdd(&cin[d], 1);  colin[p]  = s;
    int q = atomicAdd(&cout[s], 1); colout[q] = d;
}

// ---------------- batchnorm stats from bf16 hi/lo ----------------
__global__ void bn_reduce_kernel(const __nv_bfloat16* __restrict__ hh,
                                 const __nv_bfloat16* __restrict__ hl,
                                 float* __restrict__ stat) {
    int col = threadIdx.x;
    float s = 0.f, ss = 0.f;
    for (int r = blockIdx.x; r < NN; r += gridDim.x) {
        size_t o = (size_t)r * HD + col;
        float v = __bfloat162float(hh[o]) + __bfloat162float(hl[o]);
        s += v; ss += v * v;
    }
    atomicAdd(&stat[col], s);
    atomicAdd(&stat[128 + col], ss);
}

// ---------------- merged BN fold (weights + bias + bvec) ----------------
__global__ void bnfold_kernel(const float* __restrict__ lin_l, const float* __restrict__ lin_r,
                              const float* __restrict__ stat, const float* __restrict__ gamma,
                              const float* __restrict__ beta, int layer,
                              const float* __restrict__ attb, const float* __restrict__ wcat,
                              __nv_bfloat16* __restrict__ wh, __nv_bfloat16* __restrict__ wl,
                              float* __restrict__ bnb, float* __restrict__ bvec) {
    int y = blockIdx.y;
    const float invN = 1.0f / (float)NN;
    if (y < 4) {
        int e = y, d = e >> 1;
        const float* src = ((e & 1) ? lin_r : lin_l) + (size_t)(layer * 2 + d) * 16384;
        int i = blockIdx.x * 256 + threadIdx.x;
        int k = i >> 7, n = i & 127;
        float mu  = stat[k] * invN;
        float var = stat[128 + k] * invN - mu * mu;
        float s_k = gamma[k] * rsqrtf(var + 1e-5f);
        float w = src[(size_t)k * 128 + n] * s_k;
        __nv_bfloat16 h, l; split_bf16(w, h, l);
        size_t o = (size_t)OFF_PROJ + e * 16384 + (size_t)n * 128 + k;
        wh[o] = h; wl[o] = l;
    } else if (y == 4) {
        int n = blockIdx.x * 256 + threadIdx.x;
        if (n >= 512) return;
        int e = n >> 7, nn = n & 127;
        int d = e >> 1;
        const float* src = ((e & 1) ? lin_r : lin_l) + (size_t)(layer * 2 + d) * 16384;
        float acc = 0.f;
        for (int k = 0; k < 128; ++k) {
            float mu  = stat[k] * invN;
            float var = stat[128 + k] * invN - mu * mu;
            float s_k = gamma[k] * rsqrtf(var + 1e-5f);
            float t_k = beta[k] - mu * s_k;
            acc += t_k * src[(size_t)k * 128 + nn];
        }
        bnb[n] = acc;
    } else {
        if (blockIdx.x != 0) return;
        int tid = threadIdx.x;
        int dir = tid >> 7, t = tid & 127;
        const float* b = attb + (size_t)layer * 256 + dir * 128;
        const float* w = wcat + (size_t)layer * 2 * HD * HD + (size_t)dir * 128 * 128;
        float acc = 0.f;
        for (int k = 0; k < 128; ++k) acc += b[k] * w[k * 128 + t];
        bvec[tid] = acc;
    }
}

// ---------------- ffn2(l1)@wproj fold: interleaved dual accumulators ---------
__global__ void pjfold_kernel(const float* __restrict__ ffw2, const float* __restrict__ wproj,
                              const float* __restrict__ ffb2, const float* __restrict__ bproj,
                              __nv_bfloat16* __restrict__ wh, __nv_bfloat16* __restrict__ wl,
                              float* __restrict__ pjb) {
    __shared__ float w2s[128];
    int tid = threadIdx.x;
    if (blockIdx.x < 128) {
        int k = blockIdx.x;
        if (tid < 128) w2s[tid] = ffw2[(size_t)16384 + (size_t)k * 128 + tid]; // layer 1
        __syncthreads();
        int n2a = tid, n2b = tid + 256;
        float acc0 = 0.f, acc1 = 0.f;
        #pragma unroll 16
        for (int m = 0; m < 128; ++m) {
            float w = w2s[m];
            const float* row = wproj + (size_t)m * 512;
            acc0 += w * row[n2a];
            acc1 += w * row[n2b];
        }
        __nv_bfloat16 h0, l0, h1, l1;
        split_bf16(acc0, h0, l0); split_bf16(acc1, h1, l1);
        size_t oa = (size_t)OFF_PJ + (size_t)n2a * 128 + k;
        size_t ob = (size_t)OFF_PJ + (size_t)n2b * 128 + k;
        wh[oa] = h0; wl[oa] = l0;
        wh[ob] = h1; wl[ob] = l1;
    } else {
        if (tid < 128) w2s[tid] = ffb2[128 + tid];  // layer-1 bias
        __syncthreads();
        int n2a = tid, n2b = tid + 256;
        float acc0 = bproj[n2a], acc1 = bproj[n2b];
        #pragma unroll 16
        for (int m = 0; m < 128; ++m) {
            float w = w2s[m];
            const float* row = wproj + (size_t)m * 512;
            acc0 += w * row[n2a];
            acc1 += w * row[n2b];
        }
        pjb[n2a] = acc0;
        pjb[n2b] = acc1;
    }
}

// ---------------- fused 4-section inverse-norm (+gate fold) ----------------
__global__ void invnorm4_kernel(const float* __restrict__ x4, const float* __restrict__ xaux,
                                float* __restrict__ invn) {
    int w = (blockIdx.x * blockDim.x + threadIdx.x) >> 5;
    int lane = threadIdx.x & 31;
    if (w >= NN) return;
    const float* row = x4 + (size_t)w * 512;
    float ss[4];
    #pragma unroll
    for (int s = 0; s < 4; ++s) {
        float4 v = *(const float4*)&row[s * 128 + lane * 4];
        ss[s] = v.x * v.x + v.y * v.y + v.z * v.z + v.w * v.w;
    }
    #pragma unroll
    for (int off = 16; off > 0; off >>= 1) {
        ss[0] += __shfl_xor_sync(0xffffffffu, ss[0], off);
        ss[1] += __shfl_xor_sync(0xffffffffu, ss[1], off);
        ss[2] += __shfl_xor_sync(0xffffffffu, ss[2], off);
        ss[3] += __shfl_xor_sync(0xffffffffu, ss[3], off);
    }
    if (lane == 0) {
        float gw = xaux[w] * 4.0f;
        invn[0 * NN + w] = gw / fmaxf(sqrtf(ss[0]), 1e-12f);
        invn[1 * NN + w] = 1.0f / fmaxf(sqrtf(ss[1]), 1e-12f);
        invn[2 * NN + w] = gw / fmaxf(sqrtf(ss[2]), 1e-12f);
        invn[3 * NN + w] = 1.0f / fmaxf(sqrtf(ss[3]), 1e-12f);
    }
}

// ---------------- GAT-COS aggregation (warp per node, unroll x4) -------------
__global__ void gat_kernel(const int* __restrict__ roff, const int* __restrict__ col,
                           const float* __restrict__ xl, const float* __restrict__ xr,
                           const float* __restrict__ gwl, const float* __restrict__ invr,
                           __nv_bfloat16* __restrict__ aggh, __nv_bfloat16* __restrict__ aggl) {
    const int LD = 512;
    int w = (blockIdx.x * blockDim.x + threadIdx.x) >> 5;
    int lane = threadIdx.x & 31;
    if (w >= NN) return;
    float inr = invr[w];
    float4 xri = *(const float4*)&xr[(size_t)w * LD + lane * 4];
    float4 nr = make_float4(xri.x * inr, xri.y * inr, xri.z * inr, xri.w * inr);
    float s = 0.f;
    float4 acc = make_float4(0.f, 0.f, 0.f, 0.f);
    int e = roff[w], e1 = roff[w + 1];
    for (; e + 4 <= e1; e += 4) {
        int j0 = col[e], j1 = col[e + 1], j2 = col[e + 2], j3 = col[e + 3];
        float4 x0 = *(const float4*)&xl[(size_t)j0 * LD + lane * 4];
        float4 x1 = *(const float4*)&xl[(size_t)j1 * LD + lane * 4];
        float4 x2 = *(const float4*)&xl[(size_t)j2 * LD + lane * 4];
        float4 x3 = *(const float4*)&xl[(size_t)j3 * LD + lane * 4];
        float g0 = gwl[j0], g1 = gwl[j1], g2 = gwl[j2], g3 = gwl[j3];
        float p0 = nr.x * x0.x + nr.y * x0.y + nr.z * x0.z + nr.w * x0.w;
        float p1 = nr.x * x1.x + nr.y * x1.y + nr.z * x1.z + nr.w * x1.w;
        float p2 = nr.x * x2.x + nr.y * x2.y + nr.z * x2.z + nr.w * x2.w;
        float p3 = nr.x * x3.x + nr.y * x3.y + nr.z * x3.z + nr.w * x3.w;
        #pragma unroll
        for (int off = 16; off > 0; off >>= 1) {
            p0 += __shfl_xor_sync(0xffffffffu, p0, off);
            p1 += __shfl_xor_sync(0xffffffffu, p1, off);
            p2 += __shfl_xor_sync(0xffffffffu, p2, off);
            p3 += __shfl_xor_sync(0xffffffffu, p3, off);
        }
        float q0 = __expf(g0 * fabsf(p0));
        float q1 = __expf(g1 * fabsf(p1));
        float q2 = __expf(g2 * fabsf(p2));
        float q3 = __expf(g3 * fabsf(p3));
        s += (q0 + q1) + (q2 + q3);
        acc.x += q0 * x0.x + q1 * x1.x + q2 * x2.x + q3 * x3.x;
        acc.y += q0 * x0.y + q1 * x1.y + q2 * x2.y + q3 * x3.y;
        acc.z += q0 * x0.z + q1 * x1.z + q2 * x2.z + q3 * x3.z;
        acc.w += q0 * x0.w + q1 * x1.w + q2 * x2.w + q3 * x3.w;
    }
    for (; e < e1; ++e) {
        int j0 = col[e];
        float4 x0 = *(const float4*)&xl[(size_t)j0 * LD + lane * 4];
        float g0 = gwl[j0];
        float p0 = nr.x * x0.x + nr.y * x0.y + nr.z * x0.z + nr.w * x0.w;
        #pragma unroll
        for (int off = 16; off > 0; off >>= 1)
            p0 += __shfl_xor_sync(0xffffffffu, p0, off);
        float q0 = __expf(g0 * fabsf(p0));
        s += q0;
        acc.x += q0 * x0.x; acc.y += q0 * x0.y;
        acc.z += q0 * x0.z; acc.w += q0 * x0.w;
    }
    float is = 1.0f / s;
    float o[4] = {acc.x * is, acc.y * is, acc.z * is, acc.w * is};
    size_t base = (size_t)w * HD + lane * 4;
    __nv_bfloat16 h0, l0, h1, l1, h2, l2, h3, l3;
    split_bf16(o[0], h0, l0); split_bf16(o[1], h1, l1);
    split_bf16(o[2], h2, l2); split_bf16(o[3], h3, l3);
    __nv_bfloat162 ha, hb, la, lb;
    ha.x = h0; ha.y = h1; hb.x = h2; hb.y = h3;
    la.x = l0; la.y = l1; lb.x = l2; lb.y = l3;
    *(__nv_bfloat162*)&aggh[base]     = ha;
    *(__nv_bfloat162*)&aggh[base + 2] = hb;
    *(__nv_bfloat162*)&aggl[base]     = la;
    *(__nv_bfloat162*)&aggl[base + 2] = lb;
}

// ---------------- input x -> bf16 hi/lo (+ fused aux gating) ----------------
#define NXBLK 12500
__global__ void xconv_kernel(const float* __restrict__ x, __nv_bfloat16* __restrict__ xh,
                             __nv_bfloat16* __restrict__ xl,
                             const float* __restrict__ nsa, const float* __restrict__ c,
                             const float* __restrict__ d, float* __restrict__ xaux) {
    if (blockIdx.x < NXBLK) {
        int i = blockIdx.x * 256 + threadIdx.x;
        float4 v = *(const float4*)&x[i * 4];
        __nv_bfloat16 h0, l0, h1, l1, h2, l2, h3, l3;
        split_bf16(v.x, h0, l0); split_bf16(v.y, h1, l1);
        split_bf16(v.z, h2, l2); split_bf16(v.w, h3, l3);
        __nv_bfloat162 ha, hb, la, lb;
        ha.x = h0; ha.y = h1; hb.x = h2; hb.y = h3;
        la.x = l0; la.y = l1; lb.x = l2; lb.y = l3;
        *(__nv_bfloat162*)&xh[i * 4]     = ha;
        *(__nv_bfloat162*)&xh[i * 4 + 2] = hb;
        *(__nv_bfloat162*)&xl[i * 4]     = la;
        *(__nv_bfloat162*)&xl[i * 4 + 2] = lb;
    } else {
        int i = (blockIdx.x - NXBLK) * 256 + threadIdx.x;
        if (i < NN) {
            float v = c[0] * nsa[i] - d[0];
            xaux[i] = 1.0f / (1.0f + __expf(-v));
        }
    }
}

// ---------------- weight transpose + split ----------------
struct WTab {
    const float* src[8];
    int K[8];
    int N[8];
    int off[8];
};
__global__ void wconv_kernel(WTab tb, __nv_bfloat16* __restrict__ wh,
                             __nv_bfloat16* __restrict__ wl) {
    int e = blockIdx.y;
    int i = blockIdx.x * 256 + threadIdx.x;
    int K = tb.K[e], N = tb.N[e];
    if (i >= K * N) return;
    int k = i / N, n = i - k * N;
    float w = tb.src[e][(size_t)k * N + n];
    __nv_bfloat16 h, l; split_bf16(w, h, l);
    size_t o = (size_t)tb.off[e] + (size_t)n * K + k;
    wh[o] = h; wl[o] = l;
}

// ---------------- HMMA GEMM: BM=128, X/Y chunk schedule, 3-stage pipeline -----
#define SM_STRIDE 80
#define TILE_B    10240
#define BUF_BYTES 30720
template<bool GELU, int OMODE>
__global__ void __launch_bounds__(256)
hmma_kernel(const __nv_bfloat16* __restrict__ Ah, const __nv_bfloat16* __restrict__ Al,
            const __nv_bfloat16* __restrict__ Bh, const __nv_bfloat16* __restrict__ Bl,
            float* __restrict__ C, __nv_bfloat16* __restrict__ Ch,
            __nv_bfloat16* __restrict__ Cl, const float* __restrict__ bias,
            int M, int K, int ldc,
            int zsA, int zsB, int zsC, int zsBias)
{
    extern __shared__ char smem[];
    const uint32_t sbase = smem_u32(smem);
    const int tid = threadIdx.x, lane = tid & 31, wid = tid >> 5;
    const int warp_m = wid & 3, warp_n = wid >> 2;
    const int row0 = blockIdx.y * 128;
    const int col0 = blockIdx.x * 128;
    const int z = blockIdx.z;
    Ah += (size_t)z * zsA; Al += (size_t)z * zsA;
    Bh += (size_t)z * zsB; Bl += (size_t)z * zsB;
    if (C)  C  += (size_t)z * zsC;
    if (Ch) { Ch += (size_t)z * zsC; Cl += (size_t)z * zsC; }
    if (bias) bias += (size_t)z * zsBias;
    const int KB = K * 2;
    const int nkc = K >> 5;
    const int T = 2 * nkc;

    float acc[2][8][4];
    #pragma unroll
    for (int i = 0; i < 2; ++i)
        #pragma unroll
        for (int j = 0; j < 8; ++j)
            #pragma unroll
            for (int k = 0; k < 4; ++k) acc[i][j][k] = 0.f;

    auto load = [&](int c, int b) {
        bool tx = c < nkc;
        int in = tx ? c : c - nkc;
        const char* A0 = (const char*)Ah + (size_t)row0 * KB + in * 64;
        const char* B0 = (const char*)(tx ? Bh : Bl) + (size_t)col0 * KB + in * 64;
        uint32_t s  = sbase + b * BUF_BYTES;
        uint32_t s1 = s + TILE_B;
        uint32_t sB = s + 2 * TILE_B;
        #pragma unroll
        for (int i = 0; i < 2; ++i) {
            int g = tid + i * 256;
            int r = g >> 2, ch = g & 3;
            uint32_t so = r * SM_STRIDE + ch * 16;
            size_t go = (size_t)r * KB + ch * 16;
            int sz = (row0 + r < M) ? 16 : 0;
            size_t goA = sz ? go : (size_t)(ch * 16);
            cp16(s + so, A0 + goA, sz);
            cp16(sB + so, B0 + go, 16);
        }
        if (tx) {
            const char* A1 = (const char*)Al + (size_t)row0 * KB + in * 64;
            #pragma unroll
            for (int i = 0; i < 2; ++i) {
                int g = tid + i * 256;
                int r = g >> 2, ch = g & 3;
                uint32_t so = r * SM_STRIDE + ch * 16;
                int sz = (row0 + r < M) ? 16 : 0;
                const char* ga = A1 + (size_t)(sz ? r : 0) * KB + ch * 16;
                cp16(s1 + so, ga, sz);
            }
        }
        asm volatile("cp.async.commit_group;" ::: "memory");
    };

    load(0, 0);
    if (T > 1) load(1, 1);

    for (int c = 0; c < T; ++c) {
        if (c + 2 < T) {
            load(c + 2, (c + 2) % 3);
            asm volatile("cp.async.wait_group 2;" ::: "memory");
        } else if (c + 1 < T) {
            asm volatile("cp.async.wait_group 1;" ::: "memory");
        } else {
            asm volatile("cp.async.wait_group 0;" ::: "memory");
        }
        __syncthreads();

        bool tx = c < nkc;
        uint32_t s  = sbase + (c % 3) * BUF_BYTES;
        uint32_t s1 = s + TILE_B;
        uint32_t sB = s + 2 * TILE_B;
        #pragma unroll
        for (int ks = 0; ks < 2; ++ks) {
            uint32_t bb[4][4];
            #pragma unroll
            for (int fb = 0; fb < 4; ++fb) {
                int rn = warp_n * 64 + fb * 16 + (lane & 7) + ((lane >> 4) << 3);
                uint32_t bd = sB + rn * SM_STRIDE + ks * 32 + (((lane >> 3) & 1) << 4);
                LDSM4(bb[fb], bd);
            }
            uint32_t a[2][4];
            #pragma unroll
            for (int fm = 0; fm < 2; ++fm) {
                int rr = warp_m * 32 + fm * 16 + (lane & 15);
                uint32_t ad = s + rr * SM_STRIDE + ks * 32 + ((lane >> 4) << 4);
                LDSM4(a[fm], ad);
            }
            #pragma unroll
            for (int fm = 0; fm < 2; ++fm)
                #pragma unroll
                for (int fb = 0; fb < 4; ++fb) {
                    mma16816(acc[fm][fb * 2],     a[fm], bb[fb][0], bb[fb][1]);
                    mma16816(acc[fm][fb * 2 + 1], a[fm], bb[fb][2], bb[fb][3]);
                }
            if (tx) {
                #pragma unroll
                for (int fm = 0; fm < 2; ++fm) {
                    int rr = warp_m * 32 + fm * 16 + (lane & 15);
                    uint32_t ad = s1 + rr * SM_STRIDE + ks * 32 + ((lane >> 4) << 4);
                    LDSM4(a[fm], ad);
                }
                #pragma unroll
                for (int fm = 0; fm < 2; ++fm)
                    #pragma unroll
                    for (int fb = 0; fb < 4; ++fb) {
                        mma16816(acc[fm][fb * 2],     a[fm], bb[fb][0], bb[fb][1]);
                        mma16816(acc[fm][fb * 2 + 1], a[fm], bb[fb][2], bb[fb][3]);
                    }
            }
        }
        __syncthreads();
    }

    // epilogue
    #pragma unroll
    for (int fm = 0; fm < 2; ++fm) {
        int rbase = row0 + warp_m * 32 + fm * 16 + (lane >> 2);
        #pragma unroll
        for (int half = 0; half < 2; ++half) {
            int r = rbase + half * 8;
            if (r >= M) continue;
            #pragma unroll
            for (int fn = 0; fn < 8; ++fn) {
                int cc = col0 + warp_n * 64 + fn * 8 + (lane & 3) * 2;
                float v0 = acc[fm][fn][half * 2];
                float v1 = acc[fm][fn][half * 2 + 1];
                if (bias) { v0 += bias[cc]; v1 += bias[cc + 1]; }
                if (GELU) { v0 = gelu_f(v0); v1 = gelu_f(v1); }
                size_t o = (size_t)r * ldc + cc;
                if (OMODE == 0 || OMODE == 2) {
                    float2 f2 = make_float2(v0, v1);
                    *(float2*)&C[o] = f2;
                }
                if (OMODE == 1 || OMODE == 2) {
                    __nv_bfloat16 h0, l0, h1, l1;
                    split_bf16(v0, h0, l0); split_bf16(v1, h1, l1);
                    __nv_bfloat162 hp, lp;
                    hp.x = h0; hp.y = h1; lp.x = l0; lp.y = l1;
                    *(__nv_bfloat162*)&Ch[o] = hp;
                    *(__nv_bfloat162*)&Cl[o] = lp;
                }
            }
        }
    }
}

// ---------------- host ----------------
static void* sym(const void* s) {
    void* p = nullptr;
    cudaGetSymbolAddress(&p, s);
    return p;
}

#define SMEM_HM (3 * BUF_BYTES)

extern "C" void kernel_launch(void* const* d_in, const int* in_sizes, int n_in,
                              void* d_out, int out_size) {
    const float* x      = (const float*)d_in[0];
    const int*   ei     = (const int*)  d_in[1];
    const float* nsa    = (const float*)d_in[2];
    const float* c_p    = (const float*)d_in[3];
    const float* d_p    = (const float*)d_in[4];
    const float* w_in   = (const float*)d_in[5];
    const float* b_in   = (const float*)d_in[6];
    const float* bn_g   = (const float*)d_in[7];
    const float* bn_b   = (const float*)d_in[8];
    const float* lin_l  = (const float*)d_in[9];
    const float* lin_r  = (const float*)d_in[10];
    const float* attb   = (const float*)d_in[11];
    const float* wcat   = (const float*)d_in[12];
    const float* ffw1   = (const float*)d_in[13];
    const float* ffb1   = (const float*)d_in[14];
    const float* ffw2   = (const float*)d_in[15];
    const float* ffb2   = (const float*)d_in[16];
    const float* wproj  = (const float*)d_in[17];
    const float* bproj  = (const float*)d_in[18];
    float* out = (float*)d_out;

    float* p_x4   = (float*)sym(g_x4);
    float* p_invn = (float*)sym(g_invn);
    float* p_xaux = (float*)sym(g_xaux);
    float* p_bvec = (float*)sym(g_bvec);
    float* p_bn   = (float*)sym(g_bnstat);
    float* p_bnb  = (float*)sym(g_bnb);
    float* p_pjb  = (float*)sym(g_pjb);
    int* p_din  = (int*)sym(g_deg_in);
    int* p_dout = (int*)sym(g_deg_out);
    int* p_oin  = (int*)sym(g_off_in);
    int* p_oout = (int*)sym(g_off_out);
    int* p_cin  = (int*)sym(g_cur_in);
    int* p_cout = (int*)sym(g_cur_out);
    int* p_colin  = (int*)sym(g_col_in);
    int* p_colout = (int*)sym(g_col_out);
    __nv_bfloat16* p_xh   = (__nv_bfloat16*)sym(g_xh);
    __nv_bfloat16* p_xlo  = (__nv_bfloat16*)sym(g_xlo);
    __nv_bfloat16* p_hh   = (__nv_bfloat16*)sym(g_hh);
    __nv_bfloat16* p_hl   = (__nv_bfloat16*)sym(g_hl);
    __nv_bfloat16* p_aggh = (__nv_bfloat16*)sym(g_aggh);
    __nv_bfloat16* p_aggl = (__nv_bfloat16*)sym(g_aggl);
    __nv_bfloat16* p_zh   = (__nv_bfloat16*)sym(g_zh);
    __nv_bfloat16* p_zl   = (__nv_bfloat16*)sym(g_zl);
    __nv_bfloat16* p_th   = (__nv_bfloat16*)sym(g_th);
    __nv_bfloat16* p_tl   = (__nv_bfloat16*)sym(g_tl);
    __nv_bfloat16* p_wth  = (__nv_bfloat16*)sym(g_wth);
    __nv_bfloat16* p_wtl  = (__nv_bfloat16*)sym(g_wtl);

    cudaFuncSetAttribute(hmma_kernel<false, 0>, cudaFuncAttributeMaxDynamicSharedMemorySize, SMEM_HM);
    cudaFuncSetAttribute(hmma_kernel<true,  1>, cudaFuncAttributeMaxDynamicSharedMemorySize, SMEM_HM);
    cudaFuncSetAttribute(hmma_kernel<false, 1>, cudaFuncAttributeMaxDynamicSharedMemorySize, SMEM_HM);

    const int MB = (NN + 127) / 128;   // 391
    dim3 g1(1, MB), g4(4, MB), gz(1, MB, 2);
    const int gatBlocks = (NN * 32 + 255) / 256;
    const int NNHD = NN * HD;

    // ---- operand conversions (+fused aux) ----
    xconv_kernel<<<NXBLK + (NN + 255) / 256, 256>>>(x, p_xh, p_xlo, nsa, c_p, d_p, p_xaux);
    WTab tb;
    int e = 0;
    tb.src[e] = w_in; tb.K[e] = 256; tb.N[e] = 128; tb.off[e] = OFF_WIN; ++e;
    for (int i = 0; i < 4; ++i) { tb.src[e] = wcat + (size_t)i * 16384; tb.K[e] = 128; tb.N[e] = 128; tb.off[e] = OFF_WC + i * 16384; ++e; }
    for (int i = 0; i < 2; ++i) { tb.src[e] = ffw1 + (size_t)i * 32768; tb.K[e] = 256; tb.N[e] = 128; tb.off[e] = OFF_F1 + i * 32768; ++e; }
    tb.src[e] = ffw2; tb.K[e] = 128; tb.N[e] = 128; tb.off[e] = OFF_F2; ++e;   // layer 0 only
    wconv_kernel<<<dim3(256, 8), 256>>>(tb, p_wth, p_wtl);

    // ---- input projection: hh/hl = x @ w_in + b_in ----
    hmma_kernel<false, 1><<<g1, 256, SMEM_HM>>>(p_xh, p_xlo, p_wth + OFF_WIN, p_wtl + OFF_WIN,
                                                nullptr, p_hh, p_hl, b_in, NN, 256, HD, 0, 0, 0, 0);

    // ---- folded final weights (independent) ----
    pjfold_kernel<<<129, 256>>>(ffw2, wproj, ffb2, bproj, p_wth, p_wtl, p_pjb);

    // ---- CSR build ----
    zero2_kernel<<<(NN + 255) / 256, 256>>>(p_din, p_dout, NN);
    hist_kernel<<<(EE + 255) / 256, 256>>>(ei, p_din, p_dout);
    scan2_kernel<<<2, 1024>>>(p_din, p_oin, p_cin, p_colin,
                              p_dout, p_oout, p_cout, p_colout);
    scatter_kernel<<<(EE + 255) / 256, 256>>>(ei, p_cin, p_colin, p_cout, p_colout);

    for (int l = 0; l < 2; ++l) {
        zero_float_kernel<<<1, 256>>>(p_bn, 256);
        bn_reduce_kernel<<<512, 128>>>(p_hh, p_hl, p_bn);
        bnfold_kernel<<<dim3(64, 6), 256>>>(lin_l, lin_r, p_bn, bn_g + l * HD, bn_b + l * HD,
                                            l, attb, wcat, p_wth, p_wtl, p_bnb, p_bvec);

        // fused projection: x4 = h @ W' + bnb  (N=512)
        hmma_kernel<false, 0><<<g4, 256, SMEM_HM>>>(p_hh, p_hl,
            p_wth + OFF_PROJ, p_wtl + OFF_PROJ,
            p_x4, nullptr, nullptr, p_bnb, NN, 128, 512, 0, 0, 0, 0);

        invnorm4_kernel<<<gatBlocks, 256>>>(p_x4, p_xaux, p_invn);

        gat_kernel<<<gatBlocks, 256>>>(p_oin, p_colin, p_x4, p_x4 + 128,
                                       p_invn + 0 * NN, p_invn + 1 * NN, p_aggh, p_aggl);
        gat_kernel<<<gatBlocks, 256>>>(p_oout, p_colout, p_x4 + 256, p_x4 + 384,
                                       p_invn + 2 * NN, p_invn + 3 * NN,
                                       p_aggh + NNHD, p_aggl + NNHD);

        int i0 = l * 2;
        // merged wcat pair: z=0 -> aggA@wc0 -> z cols [0:128); z=1 -> aggB@wc1 -> [128:256)
        hmma_kernel<true, 1><<<gz, 256, SMEM_HM>>>(p_aggh, p_aggl,
            p_wth + OFF_WC + i0 * 16384, p_wtl + OFF_WC + i0 * 16384,
            nullptr, p_zh, p_zl, p_bvec, NN, 128, 256,
            NNHD, 16384, 128, 128);

        hmma_kernel<true, 1><<<g1, 256, SMEM_HM>>>(p_zh, p_zl, p_wth + OFF_F1 + l * 32768,
            p_wtl + OFF_F1 + l * 32768, nullptr, p_th, p_tl, ffb1 + l * HD, NN, 256, HD, 0, 0, 0, 0);

        if (l == 0) {
            hmma_kernel<false, 1><<<g1, 256, SMEM_HM>>>(p_th, p_tl, p_wth + OFF_F2,
                p_wtl + OFF_F2, nullptr, p_hh, p_hl, ffb2, NN, 128, HD, 0, 0, 0, 0);
        } else {
            // folded ffn2(l1) + final projection -> d_out [NN, 512]
            hmma_kernel<false, 0><<<g4, 256, SMEM_HM>>>(p_th, p_tl, p_wth + OFF_PJ,
                p_wtl + OFF_PJ, out, nullptr, nullptr, p_pjb, NN, 128, 512, 0, 0, 0, 0);
        }
    }
}